// round 2
// baseline (speedup 1.0000x reference)
#include <cuda_runtime.h>
#include <cstdint>

#define Bb 4
#define Cc 64
#define Hh 256
#define Ww 320
#define HW (Hh*Ww)
#define BHW (Bb*HW)
#define NOC 83          // 8 (w3) + 24 (w5) + 48 (w7) + 3 (ck)
#define NWK 83          // 9 + 25 + 49 propagation weight channels
#define EPSW 1e-6f
#define BN_EPS 1e-5f

// ---------------- device scratch (allocation-free rule: __device__ globals) ----
__device__ float g_wflat[64 * (NOC*9)];          // weights reordered: [c][oc][k]
__device__ float g_convout[(size_t)NOC * BHW];   // conv output, channel-major
__device__ float g_stats[2 * NOC];               // sums, sumsqs
__device__ float g_scale[NOC];
__device__ float g_shift[NOC];
__device__ float g_weights[(size_t)NWK * BHW];   // k-major: [0..8]=w3,[9..33]=w5,[34..82]=w7
__device__ float g_conf[3 * BHW];
__device__ float g_hnA[3 * BHW];
__device__ float g_hnB[3 * BHW];
__device__ float g_hns[3 * BHW];                 // [hn, mix@3, mix@6]

// packed dual-fp32 FMA (sm_100+): d = a*b + c on both 32-bit halves, rn rounding
#define FMA2(d, a, b, c) \
    asm("fma.rn.f32x2 %0, %1, %2, %3;" : "=l"(d) : "l"(a), "l"(b), "l"(c))

// ---------------- K0: reorder conv weights to [c][oc][9], zero stats ----------
__global__ void reorg_kernel(const float* __restrict__ w3, const float* __restrict__ w5,
                             const float* __restrict__ w7, const float* __restrict__ ck) {
    int i = blockIdx.x * blockDim.x + threadIdx.x;
    if (i < 2 * NOC) g_stats[i] = 0.f;
    if (i >= 64 * NOC * 9) return;
    int k  = i % 9;
    int t  = i / 9;
    int oc = t % NOC;
    int c  = t / NOC;
    float v;
    if (oc < 8)        v = w3[(oc      * 64 + c) * 9 + k];
    else if (oc < 32)  v = w5[((oc-8)  * 64 + c) * 9 + k];
    else if (oc < 80)  v = w7[((oc-32) * 64 + c) * 9 + k];
    else               v = ck[((oc-80) * 64 + c) * 9 + k];
    g_wflat[c * (NOC*9) + oc * 9 + k] = v;
}

// ---------------- K1: 83-channel 3x3 SAME conv, packed f32x2 (2 px/thread) ----
// Block: 128 threads = 16 pixel-pairs (32 px wide) x 8 rows.
#define TXP 16          // pixel pairs per row of the tile
#define TX2 32          // pixels wide
#define TY  8
#define TCOLS 34        // 32 + 2 halo
#define TSTRIDE 36      // padded (8B-aligned pair loads)
__global__ __launch_bounds__(128) void conv83_kernel(const float* __restrict__ fout) {
    // weights: per oc, 10 f32 pairs (9 used), each pair = weight duplicated.
    // stride 20 floats = 80B -> 16B aligned per oc for LDS.128.
    __shared__ __align__(16) float wsm[NOC * 20];
    __shared__ __align__(16) float tile[(TY+2) * TSTRIDE];

    int tid = threadIdx.x;
    int tx = tid & (TXP-1);          // pair index 0..15
    int ty = tid >> 4;               // row 0..7
    int bidx = blockIdx.x;
    const int bw = Ww / TX2;         // 10
    const int bh = Hh / TY;          // 32
    int bx = bidx % bw;
    int t2 = bidx / bw;
    int by = t2 % bh;
    int b  = t2 / bh;
    int x0 = bx * TX2, y0 = by * TY;

    uint64_t acc[NOC];
#pragma unroll
    for (int i = 0; i < NOC; i++) acc[i] = 0ull;

    for (int c = 0; c < Cc; c++) {
        const float* src = fout + ((size_t)(b * Cc + c)) * HW;
        // load input tile (with halo, zero-pad), 10 x 34 valid
        for (int i = tid; i < (TY+2)*TCOLS; i += 128) {
            int yy = i / TCOLS, xx = i - yy * TCOLS;
            int gy = y0 + yy - 1, gx = x0 + xx - 1;
            float v = 0.f;
            if (gy >= 0 && gy < Hh && gx >= 0 && gx < Ww) v = src[gy * Ww + gx];
            tile[yy * TSTRIDE + xx] = v;
        }
        // load + splat weights for this input channel
        const float* wsrc = g_wflat + c * (NOC*9);
        for (int i = tid; i < NOC*9; i += 128) {
            int oc = i / 9, k = i - oc * 9;
            float w = wsrc[i];
            wsm[oc * 20 + k * 2]     = w;
            wsm[oc * 20 + k * 2 + 1] = w;
        }
        __syncthreads();

        // build 9 packed input pairs: xp[r*3+j] = (t[2tx+j], t[2tx+j+1]) row r
        uint64_t xp[9];
#pragma unroll
        for (int r = 0; r < 3; r++) {
            const float* row = &tile[(ty + r) * TSTRIDE + 2 * tx];
            uint64_t u01 = *(const uint64_t*)(row);      // 8B aligned
            uint64_t u23 = *(const uint64_t*)(row + 2);
            uint32_t a0, a1, b0, b1;
            asm("mov.b64 {%0,%1}, %2;" : "=r"(a0), "=r"(a1) : "l"(u01));
            asm("mov.b64 {%0,%1}, %2;" : "=r"(b0), "=r"(b1) : "l"(u23));
            uint64_t u12;
            asm("mov.b64 %0, {%1,%2};" : "=l"(u12) : "r"(a1), "r"(b0));
            xp[r*3 + 0] = u01;
            xp[r*3 + 1] = u12;
            xp[r*3 + 2] = u23;
        }

        const ulonglong2* wq = (const ulonglong2*)wsm;
        const uint64_t*   wu = (const uint64_t*)wsm;
#pragma unroll
        for (int oc = 0; oc < NOC; oc++) {
            ulonglong2 w01 = wq[oc * 5 + 0];
            ulonglong2 w23 = wq[oc * 5 + 1];
            ulonglong2 w45 = wq[oc * 5 + 2];
            ulonglong2 w67 = wq[oc * 5 + 3];
            uint64_t   w8  = wu[oc * 10 + 8];
            uint64_t a = acc[oc];
            FMA2(a, w01.x, xp[0], a);
            FMA2(a, w01.y, xp[1], a);
            FMA2(a, w23.x, xp[2], a);
            FMA2(a, w23.y, xp[3], a);
            FMA2(a, w45.x, xp[4], a);
            FMA2(a, w45.y, xp[5], a);
            FMA2(a, w67.x, xp[6], a);
            FMA2(a, w67.y, xp[7], a);
            FMA2(a, w8,    xp[8], a);
            acc[oc] = a;
        }
        __syncthreads();
    }

    // store both pixels via one 8-byte store (bit-exact pair)
    size_t p = (size_t)(b * Hh + y0 + ty) * Ww + x0 + 2 * tx;
#pragma unroll
    for (int oc = 0; oc < NOC; oc++)
        *(uint64_t*)&g_convout[(size_t)oc * BHW + p] = acc[oc];
}

// ---------------- K2a: per-channel sum / sumsq ---------------------------------
__global__ void stats_kernel() {
    int oc = blockIdx.x;                 // 0..79
    const int CHUNK = BHW / 64;          // 5120
    const float* src = g_convout + (size_t)oc * BHW + blockIdx.y * CHUNK;
    float s = 0.f, s2 = 0.f;
    for (int i = threadIdx.x; i < CHUNK; i += 256) {
        float v = src[i];
        s += v;
        s2 = fmaf(v, v, s2);
    }
#pragma unroll
    for (int o = 16; o; o >>= 1) {
        s  += __shfl_down_sync(0xffffffffu, s,  o);
        s2 += __shfl_down_sync(0xffffffffu, s2, o);
    }
    __shared__ float sh[16];
    int w = threadIdx.x >> 5, l = threadIdx.x & 31;
    if (l == 0) { sh[w] = s; sh[8 + w] = s2; }
    __syncthreads();
    if (threadIdx.x == 0) {
        float a = 0.f, b2 = 0.f;
        for (int i = 0; i < 8; i++) { a += sh[i]; b2 += sh[8 + i]; }
        atomicAdd(&g_stats[oc], a);
        atomicAdd(&g_stats[NOC + oc], b2);
    }
}

// ---------------- K2b: finalize BN affine --------------------------------------
__global__ void finalize_kernel(const float* __restrict__ w3g, const float* __restrict__ w3b,
                                const float* __restrict__ w5g, const float* __restrict__ w5b,
                                const float* __restrict__ w7g, const float* __restrict__ w7b,
                                const float* __restrict__ ckb) {
    int oc = threadIdx.x;
    if (oc >= NOC) return;
    if (oc < 80) {
        float N = (float)BHW;
        float mean = g_stats[oc] / N;
        float var  = g_stats[NOC + oc] / N - mean * mean;
        float inv  = rsqrtf(var + BN_EPS);
        float g, bb;
        if (oc < 8)       { g = w3g[oc];      bb = w3b[oc]; }
        else if (oc < 32) { g = w5g[oc - 8];  bb = w5b[oc - 8]; }
        else              { g = w7g[oc - 32]; bb = w7b[oc - 32]; }
        g_scale[oc] = g * inv;
        g_shift[oc] = bb - mean * g * inv;
    } else {
        g_scale[oc] = 1.f;
        g_shift[oc] = ckb[oc - 80];   // ck bias folded here
    }
}

// ---------------- K3: per-pixel kernel generation + conf + hn init -------------
template <int NC, int PK>
__device__ __forceinline__ void gen_group(int p, int ocbase, int kbase, float sig) {
    const int KK = PK * PK;
    float w[NC];
    float s = 0.f;
#pragma unroll
    for (int j = 0; j < NC; j++) {
        float x = g_convout[(size_t)(ocbase + j) * BHW + p];
        float v = fmaxf(fmaf(g_scale[ocbase + j], x, g_shift[ocbase + j]), 0.f);
        w[j] = v;
        s += v;
    }
    float inv = 1.f / (s + EPSW);
    float mid = 1.f - s * inv;
    const int h = (KK - 1) / 2;   // == NC/2
    float full[KK];
#pragma unroll
    for (int j = 0; j < h; j++) full[j] = w[j] * inv;
    full[h] = mid;
#pragma unroll
    for (int j = 0; j < NC - h; j++) full[h + 1 + j] = w[h + j] * inv;

    float is2 = 1.f / (2.f * sig * sig);
    float t = 0.f;
#pragma unroll
    for (int k = 0; k < KK; k++) {
        const int ki = k / PK, kj = k % PK;
        float ri = -1.f + 2.f * (float)ki / (float)(PK - 1);
        float rj = -1.f + 2.f * (float)kj / (float)(PK - 1);
        float sk = __expf(-(ri * ri + rj * rj) * is2);
        full[k] *= sk;
        t += full[k];
    }
    t = fmaxf(t, 1e-7f);
    float it = 1.f / t;
#pragma unroll
    for (int k = 0; k < KK; k++) g_weights[(size_t)(kbase + k) * BHW + p] = full[k] * it;
}

__global__ void gen_weights_kernel(const float* __restrict__ hn,
                                   const float* __restrict__ ps3,
                                   const float* __restrict__ ps5,
                                   const float* __restrict__ ps7) {
    int p = blockIdx.x * blockDim.x + threadIdx.x;
    if (p >= BHW) return;
    gen_group<8, 3>(p, 0, 0, *ps3);
    gen_group<24, 5>(p, 8, 9, *ps5);
    gen_group<48, 7>(p, 32, 34, *ps7);

    // conf = softmax over the 3 ck channels (bias already in g_shift)
    float l0 = g_convout[(size_t)80 * BHW + p] + g_shift[80];
    float l1 = g_convout[(size_t)81 * BHW + p] + g_shift[81];
    float l2 = g_convout[(size_t)82 * BHW + p] + g_shift[82];
    float m = fmaxf(l0, fmaxf(l1, l2));
    float e0 = __expf(l0 - m), e1 = __expf(l1 - m), e2 = __expf(l2 - m);
    float is = 1.f / (e0 + e1 + e2);
    g_conf[p] = e0 * is;
    g_conf[BHW + p] = e1 * is;
    g_conf[2 * BHW + p] = e2 * is;

    float hv = hn[p];
    g_hnA[p] = hv; g_hnA[BHW + p] = hv; g_hnA[2 * BHW + p] = hv;
    g_hns[p] = hv;
}

// ---------------- K4: one propagation step (all three kernels) -----------------
template <int PK>
__device__ __forceinline__ float local_conv_px(const float* __restrict__ cur,
                                               int b, int y, int x, int p, int kbase) {
    const int PAD = PK / 2;
    float acc = 0.f;
    const float* plane = cur + (size_t)b * HW;
#pragma unroll
    for (int ky = 0; ky < PK; ky++) {
        int yy = y + ky - PAD;
        bool yok = (yy >= 0) & (yy < Hh);
#pragma unroll
        for (int kx = 0; kx < PK; kx++) {
            int xx = x + kx - PAD;
            float v = 0.f;
            if (yok && xx >= 0 && xx < Ww) v = __ldg(&plane[yy * Ww + xx]);
            acc = fmaf(g_weights[(size_t)(kbase + ky * PK + kx) * BHW + p], v, acc);
        }
    }
    return acc;
}

__global__ void prop_kernel(int srcA, int mixidx) {
    int p = blockIdx.x * blockDim.x + threadIdx.x;
    if (p >= BHW) return;
    const float* cur = srcA ? g_hnA : g_hnB;
    float* nxt = srcA ? g_hnB : g_hnA;
    int b = p / HW;
    int r = p - b * HW;
    int y = r / Ww;
    int x = r - y * Ww;

    float n3 = local_conv_px<3>(cur,            b, y, x, p, 0);
    float n5 = local_conv_px<5>(cur + BHW,      b, y, x, p, 9);
    float n7 = local_conv_px<7>(cur + 2 * BHW,  b, y, x, p, 34);

    nxt[p] = n3;
    nxt[BHW + p] = n5;
    nxt[2 * BHW + p] = n7;
    if (mixidx >= 0) {
        g_hns[(size_t)mixidx * BHW + p] =
            g_conf[p] * n3 + g_conf[BHW + p] * n5 + g_conf[2 * BHW + p] * n7;
    }
}

// ---------------- K5: final conv(67ch,3x3) -> softmax -> blend ------------------
#define FTX 16
#define FTY 8
__global__ __launch_bounds__(128) void final_kernel(const float* __restrict__ fout,
                                                    const float* __restrict__ ctw,
                                                    const float* __restrict__ ctb,
                                                    float* __restrict__ out) {
    __shared__ float wct[3 * 67 * 9];               // 1809 floats
    __shared__ float tile[(FTY+2)*(FTX+2)];
    int tid = threadIdx.x;
    int tx = tid & (FTX-1);
    int ty = tid >> 4;
    int bidx = blockIdx.x;
    const int bw = Ww / FTX;
    const int bh = Hh / FTY;
    int bx = bidx % bw;
    int t2 = bidx / bw;
    int by = t2 % bh;
    int b  = t2 / bh;
    int x0 = bx * FTX, y0 = by * FTY;

    for (int i = tid; i < 3 * 67 * 9; i += 128) wct[i] = ctw[i];

    float acc0 = 0.f, acc1 = 0.f, acc2 = 0.f;
    for (int ic = 0; ic < 67; ic++) {
        const float* src = (ic < 64)
            ? fout + ((size_t)(b * Cc + ic)) * HW
            : g_hns + (size_t)(ic - 64) * BHW + (size_t)b * HW;
        __syncthreads();
        for (int i = tid; i < (FTY+2)*(FTX+2); i += 128) {
            int yy = i / (FTX+2), xx = i % (FTX+2);
            int gy = y0 + yy - 1, gx = x0 + xx - 1;
            float v = 0.f;
            if (gy >= 0 && gy < Hh && gx >= 0 && gx < Ww) v = src[gy * Ww + gx];
            tile[i] = v;
        }
        __syncthreads();
        float xv[9];
#pragma unroll
        for (int ky = 0; ky < 3; ky++)
#pragma unroll
            for (int kx = 0; kx < 3; kx++)
                xv[ky * 3 + kx] = tile[(ty + ky) * (FTX+2) + tx + kx];
#pragma unroll
        for (int k = 0; k < 9; k++) {
            acc0 = fmaf(wct[(0 * 67 + ic) * 9 + k], xv[k], acc0);
            acc1 = fmaf(wct[(1 * 67 + ic) * 9 + k], xv[k], acc1);
            acc2 = fmaf(wct[(2 * 67 + ic) * 9 + k], xv[k], acc2);
        }
    }

    int p = (b * Hh + y0 + ty) * Ww + x0 + tx;
    float l0 = acc0 + ctb[0];
    float l1 = acc1 + ctb[1];
    float l2 = acc2 + ctb[2];
    float m = fmaxf(l0, fmaxf(l1, l2));
    float e0 = __expf(l0 - m), e1 = __expf(l1 - m), e2 = __expf(l2 - m);
    float is = 1.f / (e0 + e1 + e2);
    float h0v = g_hns[p], h1v = g_hns[BHW + p], h2v = g_hns[2 * BHW + p];
    out[p] = (e0 * h0v + e1 * h1v + e2 * h2v) * is;
}

// ---------------- launch --------------------------------------------------------
extern "C" void kernel_launch(void* const* d_in, const int* in_sizes, int n_in,
                              void* d_out, int out_size) {
    const float* fout = (const float*)d_in[0];
    const float* hn   = (const float*)d_in[1];
    // d_in[2] = h0 (unused by reference)
    const float* w3c  = (const float*)d_in[3];
    const float* w3g  = (const float*)d_in[4];
    const float* w3b  = (const float*)d_in[5];
    const float* w5c  = (const float*)d_in[6];
    const float* w5g  = (const float*)d_in[7];
    const float* w5b  = (const float*)d_in[8];
    const float* w7c  = (const float*)d_in[9];
    const float* w7g  = (const float*)d_in[10];
    const float* w7b  = (const float*)d_in[11];
    const float* ckw  = (const float*)d_in[12];
    const float* ckb  = (const float*)d_in[13];
    const float* ctw  = (const float*)d_in[14];
    const float* ctb  = (const float*)d_in[15];
    const float* s3   = (const float*)d_in[16];
    const float* s5   = (const float*)d_in[17];
    const float* s7   = (const float*)d_in[18];
    float* out = (float*)d_out;

    // K0: reorder weights + zero stats
    {
        int n = 64 * NOC * 9;
        reorg_kernel<<<(n + 255) / 256, 256>>>(w3c, w5c, w7c, ckw);
    }
    // K1: big conv (packed f32x2, 2 px/thread)
    conv83_kernel<<<(Ww/TX2) * (Hh/TY) * Bb, 128>>>(fout);
    // K2: BN statistics
    {
        dim3 g(80, 64);
        stats_kernel<<<g, 256>>>();
    }
    finalize_kernel<<<1, 96>>>(w3g, w3b, w5g, w5b, w7g, w7b, ckb);
    // K3: per-pixel weight generation + conf + hn init
    gen_weights_kernel<<<BHW / 256, 256>>>(hn, s3, s5, s7);
    // K4: 6 propagation iterations (ping-pong A<->B), mixes at iter 2 and 5
    prop_kernel<<<BHW / 256, 256>>>(1, -1);   // A -> B
    prop_kernel<<<BHW / 256, 256>>>(0, -1);   // B -> A
    prop_kernel<<<BHW / 256, 256>>>(1,  1);   // A -> B, mix -> hns[1]
    prop_kernel<<<BHW / 256, 256>>>(0, -1);   // B -> A
    prop_kernel<<<BHW / 256, 256>>>(1, -1);   // A -> B
    prop_kernel<<<BHW / 256, 256>>>(0,  2);   // B -> A, mix -> hns[2]
    // K5: final conv + softmax blend
    final_kernel<<<(Ww/FTX) * (Hh/FTY) * Bb, 128>>>(fout, ctw, ctb, out);
}

// round 3
// speedup vs baseline: 1.1729x; 1.1729x over previous
#include <cuda_runtime.h>
#include <cstdint>

#define Bb 4
#define Cc 64
#define Hh 256
#define Ww 320
#define HW (Hh*Ww)
#define BHW (Bb*HW)
#define NOC 83          // 8 (w3) + 24 (w5) + 48 (w7) + 3 (ck)
#define NWK 83          // 9 + 25 + 49 propagation weight channels
#define EPSW 1e-6f
#define BN_EPS 1e-5f

// ---------------- device scratch ------------------------------------------------
__device__ float g_wflat[64 * (NOC*9)];
__device__ float g_convout[(size_t)NOC * BHW];
__device__ float g_stats[2 * NOC];
__device__ float g_scale[NOC];
__device__ float g_shift[NOC];
__device__ float g_spatial[NWK];                 // spatial gaussian per k (83 values)
__device__ float g_weights[(size_t)NWK * BHW];   // k-major
__device__ float g_conf[3 * BHW];
__device__ float g_hnA[3 * BHW];
__device__ float g_hnB[3 * BHW];
__device__ float g_hns[3 * BHW];

// packed dual-fp32 FMA (sm_100+)
#define FMA2(d, a, b, c) \
    asm("fma.rn.f32x2 %0, %1, %2, %3;" : "=l"(d) : "l"(a), "l"(b), "l"(c))

__device__ __forceinline__ uint64_t pk2(float lo, float hi) {
    uint64_t r; asm("mov.b64 %0,{%1,%2};" : "=l"(r) : "f"(lo), "f"(hi)); return r;
}

__global__ void noop_kernel() {}

// ---------------- K0: reorder conv weights, zero stats --------------------------
__global__ void reorg_kernel(const float* __restrict__ w3, const float* __restrict__ w5,
                             const float* __restrict__ w7, const float* __restrict__ ck) {
    int i = blockIdx.x * blockDim.x + threadIdx.x;
    if (i < 2 * NOC) g_stats[i] = 0.f;
    if (i >= 64 * NOC * 9) return;
    int k  = i % 9;
    int t  = i / 9;
    int oc = t % NOC;
    int c  = t / NOC;
    float v;
    if (oc < 8)        v = w3[(oc      * 64 + c) * 9 + k];
    else if (oc < 32)  v = w5[((oc-8)  * 64 + c) * 9 + k];
    else if (oc < 80)  v = w7[((oc-32) * 64 + c) * 9 + k];
    else               v = ck[((oc-80) * 64 + c) * 9 + k];
    g_wflat[c * (NOC*9) + oc * 9 + k] = v;
}

// ---------------- K1: 83-channel 3x3 SAME conv (R1 scalar version) --------------
#define TX 16
#define TY 8
__global__ __launch_bounds__(128) void conv83_kernel(const float* __restrict__ fout) {
    __shared__ __align__(16) float wsm[NOC * 12];
    __shared__ float tile[(TY+2)*(TX+2)];

    int tid = threadIdx.x;
    int tx = tid & (TX-1);
    int ty = tid >> 4;
    int bidx = blockIdx.x;
    const int bw = Ww / TX;   // 20
    const int bh = Hh / TY;   // 32
    int bx = bidx % bw;
    int t2 = bidx / bw;
    int by = t2 % bh;
    int b  = t2 / bh;
    int x0 = bx * TX, y0 = by * TY;

    float acc[NOC];
#pragma unroll
    for (int i = 0; i < NOC; i++) acc[i] = 0.f;

    for (int c = 0; c < Cc; c++) {
        const float* src = fout + ((size_t)(b * Cc + c)) * HW;
        for (int i = tid; i < (TY+2)*(TX+2); i += 128) {
            int yy = i / (TX+2), xx = i % (TX+2);
            int gy = y0 + yy - 1, gx = x0 + xx - 1;
            float v = 0.f;
            if (gy >= 0 && gy < Hh && gx >= 0 && gx < Ww) v = src[gy * Ww + gx];
            tile[i] = v;
        }
        const float* wsrc = g_wflat + c * (NOC*9);
        for (int i = tid; i < NOC*9; i += 128) {
            int oc = i / 9, k = i - oc * 9;
            wsm[oc * 12 + k] = wsrc[i];
        }
        __syncthreads();

        float x0v = tile[(ty+0)*(TX+2) + tx+0];
        float x1v = tile[(ty+0)*(TX+2) + tx+1];
        float x2v = tile[(ty+0)*(TX+2) + tx+2];
        float x3v = tile[(ty+1)*(TX+2) + tx+0];
        float x4v = tile[(ty+1)*(TX+2) + tx+1];
        float x5v = tile[(ty+1)*(TX+2) + tx+2];
        float x6v = tile[(ty+2)*(TX+2) + tx+0];
        float x7v = tile[(ty+2)*(TX+2) + tx+1];
        float x8v = tile[(ty+2)*(TX+2) + tx+2];

#pragma unroll
        for (int oc = 0; oc < NOC; oc++) {
            float4 wa = *(const float4*)&wsm[oc * 12];
            float4 wb = *(const float4*)&wsm[oc * 12 + 4];
            float  w8 = wsm[oc * 12 + 8];
            float a = acc[oc];
            a = fmaf(wa.x, x0v, a); a = fmaf(wa.y, x1v, a); a = fmaf(wa.z, x2v, a);
            a = fmaf(wa.w, x3v, a); a = fmaf(wb.x, x4v, a); a = fmaf(wb.y, x5v, a);
            a = fmaf(wb.z, x6v, a); a = fmaf(wb.w, x7v, a); a = fmaf(w8,  x8v, a);
            acc[oc] = a;
        }
        __syncthreads();
    }

    int p = (b * Hh + y0 + ty) * Ww + x0 + tx;
#pragma unroll
    for (int oc = 0; oc < NOC; oc++) g_convout[(size_t)oc * BHW + p] = acc[oc];
}

// ---------------- K2a: per-channel sum / sumsq ----------------------------------
__global__ void stats_kernel() {
    int oc = blockIdx.x;
    const int CHUNK = BHW / 64;
    const float* src = g_convout + (size_t)oc * BHW + blockIdx.y * CHUNK;
    float s = 0.f, s2 = 0.f;
    for (int i = threadIdx.x; i < CHUNK; i += 256) {
        float v = src[i];
        s += v;
        s2 = fmaf(v, v, s2);
    }
#pragma unroll
    for (int o = 16; o; o >>= 1) {
        s  += __shfl_down_sync(0xffffffffu, s,  o);
        s2 += __shfl_down_sync(0xffffffffu, s2, o);
    }
    __shared__ float sh[16];
    int w = threadIdx.x >> 5, l = threadIdx.x & 31;
    if (l == 0) { sh[w] = s; sh[8 + w] = s2; }
    __syncthreads();
    if (threadIdx.x == 0) {
        float a = 0.f, b2 = 0.f;
        for (int i = 0; i < 8; i++) { a += sh[i]; b2 += sh[8 + i]; }
        atomicAdd(&g_stats[oc], a);
        atomicAdd(&g_stats[NOC + oc], b2);
    }
}

// ---------------- K2b: finalize BN affine + spatial table -----------------------
__global__ void finalize_kernel(const float* __restrict__ w3g, const float* __restrict__ w3b,
                                const float* __restrict__ w5g, const float* __restrict__ w5b,
                                const float* __restrict__ w7g, const float* __restrict__ w7b,
                                const float* __restrict__ ckb,
                                const float* __restrict__ ps3,
                                const float* __restrict__ ps5,
                                const float* __restrict__ ps7) {
    int oc = threadIdx.x;
    if (oc < NWK) {
        // spatial gaussian value for global k index oc
        int pk, kk, kb;
        float sig;
        if (oc < 9)       { pk = 3; kb = 0;  sig = *ps3; }
        else if (oc < 34) { pk = 5; kb = 9;  sig = *ps5; }
        else              { pk = 7; kb = 34; sig = *ps7; }
        kk = oc - kb;
        int ki = kk / pk, kj = kk % pk;
        float ri = -1.f + 2.f * (float)ki / (float)(pk - 1);
        float rj = -1.f + 2.f * (float)kj / (float)(pk - 1);
        g_spatial[oc] = __expf(-(ri * ri + rj * rj) / (2.f * sig * sig));
    }
    if (oc >= NOC) return;
    if (oc < 80) {
        float N = (float)BHW;
        float mean = g_stats[oc] / N;
        float var  = g_stats[NOC + oc] / N - mean * mean;
        float inv  = rsqrtf(var + BN_EPS);
        float g, bb;
        if (oc < 8)       { g = w3g[oc];      bb = w3b[oc]; }
        else if (oc < 32) { g = w5g[oc - 8];  bb = w5b[oc - 8]; }
        else              { g = w7g[oc - 32]; bb = w7b[oc - 32]; }
        g_scale[oc] = g * inv;
        g_shift[oc] = bb - mean * g * inv;
    } else {
        g_scale[oc] = 1.f;
        g_shift[oc] = ckb[oc - 80];
    }
}

// ---------------- K3: per-pixel kernel generation (2 px/thread) -----------------
template <int NC, int PK>
__device__ __forceinline__ void gen_group2(int p, int ocbase, int kbase, const float* __restrict__ sp) {
    const int KK = PK * PK;
    float w0[NC], w1[NC];
    float s0 = 0.f, s1 = 0.f;
#pragma unroll
    for (int j = 0; j < NC; j++) {
        float2 x = *(const float2*)&g_convout[(size_t)(ocbase + j) * BHW + p];
        float sc = g_scale[ocbase + j], sh = g_shift[ocbase + j];
        float a = fmaxf(fmaf(sc, x.x, sh), 0.f);
        float b = fmaxf(fmaf(sc, x.y, sh), 0.f);
        w0[j] = a; w1[j] = b;
        s0 += a;  s1 += b;
    }
    float i0 = 1.f / (s0 + EPSW), i1 = 1.f / (s1 + EPSW);
    float mid0 = 1.f - s0 * i0,   mid1 = 1.f - s1 * i1;
    const int h = (KK - 1) / 2;
    float f0[KK], f1[KK];
#pragma unroll
    for (int j = 0; j < h; j++) { f0[j] = w0[j] * i0; f1[j] = w1[j] * i1; }
    f0[h] = mid0; f1[h] = mid1;
#pragma unroll
    for (int j = 0; j < NC - h; j++) { f0[h+1+j] = w0[h+j] * i0; f1[h+1+j] = w1[h+j] * i1; }

    float t0 = 0.f, t1 = 0.f;
#pragma unroll
    for (int k = 0; k < KK; k++) {
        float sk = sp[kbase + k];
        f0[k] *= sk; f1[k] *= sk;
        t0 += f0[k]; t1 += f1[k];
    }
    float it0 = 1.f / fmaxf(t0, 1e-7f);
    float it1 = 1.f / fmaxf(t1, 1e-7f);
#pragma unroll
    for (int k = 0; k < KK; k++) {
        float2 o; o.x = f0[k] * it0; o.y = f1[k] * it1;
        *(float2*)&g_weights[(size_t)(kbase + k) * BHW + p] = o;
    }
}

__global__ __launch_bounds__(256) void gen_weights_kernel(const float* __restrict__ hn) {
    __shared__ float ssp[NWK];
    int tid = threadIdx.x;
    if (tid < NWK) ssp[tid] = g_spatial[tid];
    __syncthreads();
    int p = 2 * (blockIdx.x * 256 + tid);
    if (p >= BHW) return;
    gen_group2<8, 3>(p, 0, 0, ssp);
    gen_group2<24, 5>(p, 8, 9, ssp);
    gen_group2<48, 7>(p, 32, 34, ssp);

    float2 l0 = *(const float2*)&g_convout[(size_t)80 * BHW + p];
    float2 l1 = *(const float2*)&g_convout[(size_t)81 * BHW + p];
    float2 l2 = *(const float2*)&g_convout[(size_t)82 * BHW + p];
    float s80 = g_shift[80], s81 = g_shift[81], s82 = g_shift[82];
#pragma unroll
    for (int hfi = 0; hfi < 2; hfi++) {
        float a = (hfi ? l0.y : l0.x) + s80;
        float b = (hfi ? l1.y : l1.x) + s81;
        float c = (hfi ? l2.y : l2.x) + s82;
        float m = fmaxf(a, fmaxf(b, c));
        float e0 = __expf(a - m), e1 = __expf(b - m), e2 = __expf(c - m);
        float is = 1.f / (e0 + e1 + e2);
        g_conf[p + hfi] = e0 * is;
        g_conf[BHW + p + hfi] = e1 * is;
        g_conf[2 * BHW + p + hfi] = e2 * is;
    }
    float2 hv = *(const float2*)&hn[p];
    *(float2*)&g_hnA[p] = hv;
    *(float2*)&g_hnA[BHW + p] = hv;
    *(float2*)&g_hnA[2 * BHW + p] = hv;
    *(float2*)&g_hns[p] = hv;
}

// ---------------- K4: propagation, smem-tiled, 4 px/thread, FFMA2 ---------------
#define PTW 64
#define PTH 16
#define PSW 72            // smem row stride (70 cols used)
// build the 9 consecutive value-pairs (v_j, v_{j+1}), j=0..8, from 10 values at rowp[0..9]
__device__ __forceinline__ void build_pr(const float* __restrict__ rowp, uint64_t pr[9]) {
    float2 f0 = *(const float2*)(rowp);
    float2 f1 = *(const float2*)(rowp + 2);
    float2 f2 = *(const float2*)(rowp + 4);
    float2 f3 = *(const float2*)(rowp + 6);
    float2 f4 = *(const float2*)(rowp + 8);
    pr[0] = pk2(f0.x, f0.y);
    pr[1] = pk2(f0.y, f1.x);
    pr[2] = pk2(f1.x, f1.y);
    pr[3] = pk2(f1.y, f2.x);
    pr[4] = pk2(f2.x, f2.y);
    pr[5] = pk2(f2.y, f3.x);
    pr[6] = pk2(f3.x, f3.y);
    pr[7] = pk2(f3.y, f4.x);
    pr[8] = pk2(f4.x, f4.y);
}

__global__ __launch_bounds__(256) void prop_kernel(int srcA, int mixidx) {
    __shared__ __align__(16) float sh[3][PTH + 6][PSW];
    const float* cur = srcA ? g_hnA : g_hnB;
    float* nxt = srcA ? g_hnB : g_hnA;

    int tid = threadIdx.x;
    int tx = tid & 15;            // 0..15 -> 4 px each
    int ty = tid >> 4;            // 0..15
    int bx = blockIdx.x;          // 0..4
    int by = blockIdx.y;          // 0..15
    int b  = blockIdx.z;          // 0..3
    int x0 = bx * PTW, y0 = by * PTH;

    // fill 3 channels, rows 0..21, cols 0..69, zero-padded
#pragma unroll
    for (int c = 0; c < 3; c++) {
        const float* plane = cur + (size_t)c * BHW + (size_t)b * HW;
        for (int i = tid; i < (PTH + 6) * 70; i += 256) {
            int r = i / 70, col = i - r * 70;
            int gy = y0 + r - 3, gx = x0 + col - 3;
            float v = 0.f;
            if (gy >= 0 && gy < Hh && gx >= 0 && gx < Ww) v = plane[gy * Ww + gx];
            sh[c][r][col] = v;
        }
    }
    __syncthreads();

    int xl = tx * 4;
    int p0 = (b * Hh + y0 + ty) * Ww + x0 + xl;

    uint64_t a3p0 = 0, a3p1 = 0, a5p0 = 0, a5p1 = 0, a7p0 = 0, a7p1 = 0;
    uint64_t pr[9];

    // w3: channel 0, taps dy,dx in -1..1, k = 0 + (dy+1)*3 + (dx+1)
#pragma unroll
    for (int ky = 0; ky < 3; ky++) {
        build_pr(&sh[0][ty + 2 + ky][xl], pr);
#pragma unroll
        for (int kx = 0; kx < 3; kx++) {
            const ulonglong2 wq = *(const ulonglong2*)&g_weights[(size_t)(0 + ky * 3 + kx) * BHW + p0];
            FMA2(a3p0, wq.x, pr[kx + 2], a3p0);
            FMA2(a3p1, wq.y, pr[kx + 4], a3p1);
        }
    }
    // w5: channel 1, k = 9 + ky*5 + kx
#pragma unroll
    for (int ky = 0; ky < 5; ky++) {
        build_pr(&sh[1][ty + 1 + ky][xl], pr);
#pragma unroll
        for (int kx = 0; kx < 5; kx++) {
            const ulonglong2 wq = *(const ulonglong2*)&g_weights[(size_t)(9 + ky * 5 + kx) * BHW + p0];
            FMA2(a5p0, wq.x, pr[kx + 1], a5p0);
            FMA2(a5p1, wq.y, pr[kx + 3], a5p1);
        }
    }
    // w7: channel 2, k = 34 + ky*7 + kx
#pragma unroll
    for (int ky = 0; ky < 7; ky++) {
        build_pr(&sh[2][ty + ky][xl], pr);
#pragma unroll
        for (int kx = 0; kx < 7; kx++) {
            const ulonglong2 wq = *(const ulonglong2*)&g_weights[(size_t)(34 + ky * 7 + kx) * BHW + p0];
            FMA2(a7p0, wq.x, pr[kx], a7p0);
            FMA2(a7p1, wq.y, pr[kx + 2], a7p1);
        }
    }

    *(uint64_t*)&nxt[p0]               = a3p0;
    *(uint64_t*)&nxt[p0 + 2]           = a3p1;
    *(uint64_t*)&nxt[BHW + p0]         = a5p0;
    *(uint64_t*)&nxt[BHW + p0 + 2]     = a5p1;
    *(uint64_t*)&nxt[2 * BHW + p0]     = a7p0;
    *(uint64_t*)&nxt[2 * BHW + p0 + 2] = a7p1;

    if (mixidx >= 0) {
        const ulonglong2 c3 = *(const ulonglong2*)&g_conf[p0];
        const ulonglong2 c5 = *(const ulonglong2*)&g_conf[BHW + p0];
        const ulonglong2 c7 = *(const ulonglong2*)&g_conf[2 * BHW + p0];
        uint64_t m0 = 0, m1 = 0;
        FMA2(m0, c3.x, a3p0, m0); FMA2(m0, c5.x, a5p0, m0); FMA2(m0, c7.x, a7p0, m0);
        FMA2(m1, c3.y, a3p1, m1); FMA2(m1, c5.y, a5p1, m1); FMA2(m1, c7.y, a7p1, m1);
        *(uint64_t*)&g_hns[(size_t)mixidx * BHW + p0]     = m0;
        *(uint64_t*)&g_hns[(size_t)mixidx * BHW + p0 + 2] = m1;
    }
}

// ---------------- K5: final conv(67ch,3x3) -> softmax -> blend ------------------
#define FTX 16
#define FTY 8
__global__ __launch_bounds__(128) void final_kernel(const float* __restrict__ fout,
                                                    const float* __restrict__ ctw,
                                                    const float* __restrict__ ctb,
                                                    float* __restrict__ out) {
    __shared__ float wct[3 * 67 * 9];
    __shared__ float tile[(FTY+2)*(FTX+2)];
    int tid = threadIdx.x;
    int tx = tid & (FTX-1);
    int ty = tid >> 4;
    int bidx = blockIdx.x;
    const int bw = Ww / FTX;
    const int bh = Hh / FTY;
    int bx = bidx % bw;
    int t2 = bidx / bw;
    int by = t2 % bh;
    int b  = t2 / bh;
    int x0 = bx * FTX, y0 = by * FTY;

    for (int i = tid; i < 3 * 67 * 9; i += 128) wct[i] = ctw[i];

    float acc0 = 0.f, acc1 = 0.f, acc2 = 0.f;
    for (int ic = 0; ic < 67; ic++) {
        const float* src = (ic < 64)
            ? fout + ((size_t)(b * Cc + ic)) * HW
            : g_hns + (size_t)(ic - 64) * BHW + (size_t)b * HW;
        __syncthreads();
        for (int i = tid; i < (FTY+2)*(FTX+2); i += 128) {
            int yy = i / (FTX+2), xx = i % (FTX+2);
            int gy = y0 + yy - 1, gx = x0 + xx - 1;
            float v = 0.f;
            if (gy >= 0 && gy < Hh && gx >= 0 && gx < Ww) v = src[gy * Ww + gx];
            tile[i] = v;
        }
        __syncthreads();
        float xv[9];
#pragma unroll
        for (int ky = 0; ky < 3; ky++)
#pragma unroll
            for (int kx = 0; kx < 3; kx++)
                xv[ky * 3 + kx] = tile[(ty + ky) * (FTX+2) + tx + kx];
#pragma unroll
        for (int k = 0; k < 9; k++) {
            acc0 = fmaf(wct[(0 * 67 + ic) * 9 + k], xv[k], acc0);
            acc1 = fmaf(wct[(1 * 67 + ic) * 9 + k], xv[k], acc1);
            acc2 = fmaf(wct[(2 * 67 + ic) * 9 + k], xv[k], acc2);
        }
    }

    int p = (b * Hh + y0 + ty) * Ww + x0 + tx;
    float l0 = acc0 + ctb[0];
    float l1 = acc1 + ctb[1];
    float l2 = acc2 + ctb[2];
    float m = fmaxf(l0, fmaxf(l1, l2));
    float e0 = __expf(l0 - m), e1 = __expf(l1 - m), e2 = __expf(l2 - m);
    float is = 1.f / (e0 + e1 + e2);
    float h0v = g_hns[p], h1v = g_hns[BHW + p], h2v = g_hns[2 * BHW + p];
    out[p] = (e0 * h0v + e1 * h1v + e2 * h2v) * is;
}

// ---------------- launch --------------------------------------------------------
extern "C" void kernel_launch(void* const* d_in, const int* in_sizes, int n_in,
                              void* d_out, int out_size) {
    const float* fout = (const float*)d_in[0];
    const float* hn   = (const float*)d_in[1];
    const float* w3c  = (const float*)d_in[3];
    const float* w3g  = (const float*)d_in[4];
    const float* w3b  = (const float*)d_in[5];
    const float* w5c  = (const float*)d_in[6];
    const float* w5g  = (const float*)d_in[7];
    const float* w5b  = (const float*)d_in[8];
    const float* w7c  = (const float*)d_in[9];
    const float* w7g  = (const float*)d_in[10];
    const float* w7b  = (const float*)d_in[11];
    const float* ckw  = (const float*)d_in[12];
    const float* ckb  = (const float*)d_in[13];
    const float* ctw  = (const float*)d_in[14];
    const float* ctb  = (const float*)d_in[15];
    const float* s3   = (const float*)d_in[16];
    const float* s5   = (const float*)d_in[17];
    const float* s7   = (const float*)d_in[18];
    float* out = (float*)d_out;

    // launch 1: reorg
    {
        int n = 64 * NOC * 9;
        reorg_kernel<<<(n + 255) / 256, 256>>>(w3c, w5c, w7c, ckw);
    }
    // launches 2,3: no-ops so the profiled slot (4th launch) is conv83
    noop_kernel<<<1, 32>>>();
    noop_kernel<<<1, 32>>>();
    // launch 4: big conv (profiled)
    conv83_kernel<<<(Ww/TX) * (Hh/TY) * Bb, 128>>>(fout);
    // BN statistics
    {
        dim3 g(80, 64);
        stats_kernel<<<g, 256>>>();
    }
    finalize_kernel<<<1, 96>>>(w3g, w3b, w5g, w5b, w7g, w7b, ckb, s3, s5, s7);
    // per-pixel weight generation + conf + hn init (2 px/thread)
    gen_weights_kernel<<<BHW / 512, 256>>>(hn);
    // 6 propagation iterations
    {
        dim3 g(Ww / PTW, Hh / PTH, Bb);
        prop_kernel<<<g, 256>>>(1, -1);
        prop_kernel<<<g, 256>>>(0, -1);
        prop_kernel<<<g, 256>>>(1,  1);
        prop_kernel<<<g, 256>>>(0, -1);
        prop_kernel<<<g, 256>>>(1, -1);
        prop_kernel<<<g, 256>>>(0,  2);
    }
    // final conv + softmax blend
    final_kernel<<<(Ww/FTX) * (Hh/FTY) * Bb, 128>>>(fout, ctw, ctb, out);
}

// round 4
// speedup vs baseline: 1.1957x; 1.0195x over previous
#include <cuda_runtime.h>
#include <cstdint>

#define Bb 4
#define Cc 64
#define Hh 256
#define Ww 320
#define HW (Hh*Ww)
#define BHW (Bb*HW)
#define NOC 83          // 8 (w3) + 24 (w5) + 48 (w7) + 3 (ck)
#define NOCP 84         // padded to 3 groups of 28
#define NWK 83
#define EPSW 1e-6f
#define BN_EPS 1e-5f

// ---------------- device scratch ------------------------------------------------
__device__ float g_wflat[64 * (NOCP*9)];
__device__ float g_convout[(size_t)NOCP * BHW];
__device__ float g_stats[2 * NOC];
__device__ float g_scale[NOC];
__device__ float g_shift[NOC];
__device__ float g_spatial[NWK];
__device__ float g_weights[(size_t)NWK * BHW];
__device__ float g_conf[3 * BHW];
__device__ float g_hnA[3 * BHW];
__device__ float g_hnB[3 * BHW];
__device__ float g_hns[3 * BHW];

// packed dual-fp32 FMA (sm_100+)
#define FMA2(d, a, b, c) \
    asm("fma.rn.f32x2 %0, %1, %2, %3;" : "=l"(d) : "l"(a), "l"(b), "l"(c))

__device__ __forceinline__ uint64_t pk2(float lo, float hi) {
    uint64_t r; asm("mov.b64 %0,{%1,%2};" : "=l"(r) : "f"(lo), "f"(hi)); return r;
}

__global__ void noop_kernel() {}

// ---------------- K0: reorder conv weights (pad oc 83 with zeros) --------------
__global__ void reorg_kernel(const float* __restrict__ w3, const float* __restrict__ w5,
                             const float* __restrict__ w7, const float* __restrict__ ck) {
    int i = blockIdx.x * blockDim.x + threadIdx.x;
    if (i < 2 * NOC) g_stats[i] = 0.f;
    if (i >= 64 * NOCP * 9) return;
    int k  = i % 9;
    int t  = i / 9;
    int oc = t % NOCP;
    int c  = t / NOCP;
    float v;
    if (oc < 8)        v = w3[(oc      * 64 + c) * 9 + k];
    else if (oc < 32)  v = w5[((oc-8)  * 64 + c) * 9 + k];
    else if (oc < 80)  v = w7[((oc-32) * 64 + c) * 9 + k];
    else if (oc < 83)  v = ck[((oc-80) * 64 + c) * 9 + k];
    else               v = 0.f;
    g_wflat[c * (NOCP*9) + oc * 9 + k] = v;
}

// ---------------- K1: 3x3 conv, 28 oc per block, 4 px per thread ----------------
#define CTY 8
#define CTILEW 64
#define CSTR 68          // smem row stride (66 used), 272B = 16B aligned
__global__ __launch_bounds__(128) void conv83_kernel(const float* __restrict__ fout) {
    __shared__ __align__(16) float wsm[28 * 12];
    __shared__ __align__(16) float tile[(CTY+2) * CSTR];

    int tid = threadIdx.x;
    int tx = tid & 15;           // 0..15, 4 px each
    int ty = tid >> 4;           // 0..7
    int gb = blockIdx.x;         // group fastest for L2 tile sharing
    int grp = gb % 3;
    int bx  = gb / 3;            // 0..4
    int by  = blockIdx.y;        // 0..31
    int b   = blockIdx.z;
    int x0 = bx * CTILEW, y0 = by * CTY;
    int ocbase = grp * 28;

    float4 acc[28];
#pragma unroll
    for (int i = 0; i < 28; i++) acc[i] = make_float4(0.f, 0.f, 0.f, 0.f);

    for (int c = 0; c < Cc; c++) {
        const float* src = fout + ((size_t)(b * Cc + c)) * HW;
        // input tile 10 x 66 (halo 1), zero-padded
        for (int i = tid; i < 10 * 66; i += 128) {
            int r = i / 66, col = i - r * 66;
            int gy = y0 + r - 1, gx = x0 + col - 1;
            float v = 0.f;
            if (gy >= 0 && gy < Hh && gx >= 0 && gx < Ww) v = src[gy * Ww + gx];
            tile[r * CSTR + col] = v;
        }
        // 28 x 9 weights for this channel/group
        const float* wsrc = g_wflat + c * (NOCP*9) + ocbase * 9;
        for (int i = tid; i < 28 * 9; i += 128) {
            int oc = i / 9, k = i - oc * 9;
            wsm[oc * 12 + k] = wsrc[i];
        }
        __syncthreads();

        // 3 rows x 6 input values per thread (4 px + 2 halo)
        float xv[3][6];
#pragma unroll
        for (int r = 0; r < 3; r++) {
            const float* row = &tile[(ty + r) * CSTR + tx * 4];
            float4 q = *(const float4*)row;
            float2 d = *(const float2*)(row + 4);
            xv[r][0] = q.x; xv[r][1] = q.y; xv[r][2] = q.z;
            xv[r][3] = q.w; xv[r][4] = d.x; xv[r][5] = d.y;
        }

#pragma unroll
        for (int oc = 0; oc < 28; oc++) {
            float4 wa = *(const float4*)&wsm[oc * 12];
            float4 wb = *(const float4*)&wsm[oc * 12 + 4];
            float  w8 = wsm[oc * 12 + 8];
            float w[9] = {wa.x, wa.y, wa.z, wa.w, wb.x, wb.y, wb.z, wb.w, w8};
            float4 a = acc[oc];
#pragma unroll
            for (int ky = 0; ky < 3; ky++) {
#pragma unroll
                for (int kx = 0; kx < 3; kx++) {
                    float wk = w[ky * 3 + kx];
                    a.x = fmaf(wk, xv[ky][0 + kx], a.x);
                    a.y = fmaf(wk, xv[ky][1 + kx], a.y);
                    a.z = fmaf(wk, xv[ky][2 + kx], a.z);
                    a.w = fmaf(wk, xv[ky][3 + kx], a.w);
                }
            }
            acc[oc] = a;
        }
        __syncthreads();
    }

    int p = (b * Hh + y0 + ty) * Ww + x0 + tx * 4;
#pragma unroll
    for (int oc = 0; oc < 28; oc++)
        *(float4*)&g_convout[(size_t)(ocbase + oc) * BHW + p] = acc[oc];
}

// ---------------- K2a: per-channel sum / sumsq ----------------------------------
__global__ void stats_kernel() {
    int oc = blockIdx.x;
    const int CHUNK = BHW / 64;
    const float* src = g_convout + (size_t)oc * BHW + blockIdx.y * CHUNK;
    float s = 0.f, s2 = 0.f;
    for (int i = threadIdx.x; i < CHUNK; i += 256) {
        float v = src[i];
        s += v;
        s2 = fmaf(v, v, s2);
    }
#pragma unroll
    for (int o = 16; o; o >>= 1) {
        s  += __shfl_down_sync(0xffffffffu, s,  o);
        s2 += __shfl_down_sync(0xffffffffu, s2, o);
    }
    __shared__ float sh[16];
    int w = threadIdx.x >> 5, l = threadIdx.x & 31;
    if (l == 0) { sh[w] = s; sh[8 + w] = s2; }
    __syncthreads();
    if (threadIdx.x == 0) {
        float a = 0.f, b2 = 0.f;
        for (int i = 0; i < 8; i++) { a += sh[i]; b2 += sh[8 + i]; }
        atomicAdd(&g_stats[oc], a);
        atomicAdd(&g_stats[NOC + oc], b2);
    }
}

// ---------------- K2b: finalize BN affine + spatial table -----------------------
__global__ void finalize_kernel(const float* __restrict__ w3g, const float* __restrict__ w3b,
                                const float* __restrict__ w5g, const float* __restrict__ w5b,
                                const float* __restrict__ w7g, const float* __restrict__ w7b,
                                const float* __restrict__ ckb,
                                const float* __restrict__ ps3,
                                const float* __restrict__ ps5,
                                const float* __restrict__ ps7) {
    int oc = threadIdx.x;
    if (oc < NWK) {
        int pk, kk, kb;
        float sig;
        if (oc < 9)       { pk = 3; kb = 0;  sig = *ps3; }
        else if (oc < 34) { pk = 5; kb = 9;  sig = *ps5; }
        else              { pk = 7; kb = 34; sig = *ps7; }
        kk = oc - kb;
        int ki = kk / pk, kj = kk % pk;
        float ri = -1.f + 2.f * (float)ki / (float)(pk - 1);
        float rj = -1.f + 2.f * (float)kj / (float)(pk - 1);
        g_spatial[oc] = __expf(-(ri * ri + rj * rj) / (2.f * sig * sig));
    }
    if (oc >= NOC) return;
    if (oc < 80) {
        float N = (float)BHW;
        float mean = g_stats[oc] / N;
        float var  = g_stats[NOC + oc] / N - mean * mean;
        float inv  = rsqrtf(var + BN_EPS);
        float g, bb;
        if (oc < 8)       { g = w3g[oc];      bb = w3b[oc]; }
        else if (oc < 32) { g = w5g[oc - 8];  bb = w5b[oc - 8]; }
        else              { g = w7g[oc - 32]; bb = w7b[oc - 32]; }
        g_scale[oc] = g * inv;
        g_shift[oc] = bb - mean * g * inv;
    } else {
        g_scale[oc] = 1.f;
        g_shift[oc] = ckb[oc - 80];
    }
}

// ---------------- K3: per-pixel kernel generation (2 px/thread) -----------------
template <int NC, int PK>
__device__ __forceinline__ void gen_group2(int p, int ocbase, int kbase, const float* __restrict__ sp) {
    const int KK = PK * PK;
    float w0[NC], w1[NC];
    float s0 = 0.f, s1 = 0.f;
#pragma unroll
    for (int j = 0; j < NC; j++) {
        float2 x = *(const float2*)&g_convout[(size_t)(ocbase + j) * BHW + p];
        float sc = g_scale[ocbase + j], sh = g_shift[ocbase + j];
        float a = fmaxf(fmaf(sc, x.x, sh), 0.f);
        float b = fmaxf(fmaf(sc, x.y, sh), 0.f);
        w0[j] = a; w1[j] = b;
        s0 += a;  s1 += b;
    }
    float i0 = 1.f / (s0 + EPSW), i1 = 1.f / (s1 + EPSW);
    float mid0 = 1.f - s0 * i0,   mid1 = 1.f - s1 * i1;
    const int h = (KK - 1) / 2;
    float f0[KK], f1[KK];
#pragma unroll
    for (int j = 0; j < h; j++) { f0[j] = w0[j] * i0; f1[j] = w1[j] * i1; }
    f0[h] = mid0; f1[h] = mid1;
#pragma unroll
    for (int j = 0; j < NC - h; j++) { f0[h+1+j] = w0[h+j] * i0; f1[h+1+j] = w1[h+j] * i1; }

    float t0 = 0.f, t1 = 0.f;
#pragma unroll
    for (int k = 0; k < KK; k++) {
        float sk = sp[kbase + k];
        f0[k] *= sk; f1[k] *= sk;
        t0 += f0[k]; t1 += f1[k];
    }
    float it0 = 1.f / fmaxf(t0, 1e-7f);
    float it1 = 1.f / fmaxf(t1, 1e-7f);
#pragma unroll
    for (int k = 0; k < KK; k++) {
        float2 o; o.x = f0[k] * it0; o.y = f1[k] * it1;
        *(float2*)&g_weights[(size_t)(kbase + k) * BHW + p] = o;
    }
}

__global__ __launch_bounds__(256) void gen_weights_kernel(const float* __restrict__ hn) {
    __shared__ float ssp[NWK];
    int tid = threadIdx.x;
    if (tid < NWK) ssp[tid] = g_spatial[tid];
    __syncthreads();
    int p = 2 * (blockIdx.x * 256 + tid);
    if (p >= BHW) return;
    gen_group2<8, 3>(p, 0, 0, ssp);
    gen_group2<24, 5>(p, 8, 9, ssp);
    gen_group2<48, 7>(p, 32, 34, ssp);

    float2 l0 = *(const float2*)&g_convout[(size_t)80 * BHW + p];
    float2 l1 = *(const float2*)&g_convout[(size_t)81 * BHW + p];
    float2 l2 = *(const float2*)&g_convout[(size_t)82 * BHW + p];
    float s80 = g_shift[80], s81 = g_shift[81], s82 = g_shift[82];
#pragma unroll
    for (int hfi = 0; hfi < 2; hfi++) {
        float a = (hfi ? l0.y : l0.x) + s80;
        float b = (hfi ? l1.y : l1.x) + s81;
        float c = (hfi ? l2.y : l2.x) + s82;
        float m = fmaxf(a, fmaxf(b, c));
        float e0 = __expf(a - m), e1 = __expf(b - m), e2 = __expf(c - m);
        float is = 1.f / (e0 + e1 + e2);
        g_conf[p + hfi] = e0 * is;
        g_conf[BHW + p + hfi] = e1 * is;
        g_conf[2 * BHW + p + hfi] = e2 * is;
    }
    float2 hv = *(const float2*)&hn[p];
    *(float2*)&g_hnA[p] = hv;
    *(float2*)&g_hnA[BHW + p] = hv;
    *(float2*)&g_hnA[2 * BHW + p] = hv;
    *(float2*)&g_hns[p] = hv;
}

// ---------------- K4: propagation, smem-tiled, 4 px/thread, FFMA2 ---------------
#define PTW 64
#define PTH 16
#define PSW 72
__device__ __forceinline__ void build_pr(const float* __restrict__ rowp, uint64_t pr[9]) {
    float2 f0 = *(const float2*)(rowp);
    float2 f1 = *(const float2*)(rowp + 2);
    float2 f2 = *(const float2*)(rowp + 4);
    float2 f3 = *(const float2*)(rowp + 6);
    float2 f4 = *(const float2*)(rowp + 8);
    pr[0] = pk2(f0.x, f0.y);
    pr[1] = pk2(f0.y, f1.x);
    pr[2] = pk2(f1.x, f1.y);
    pr[3] = pk2(f1.y, f2.x);
    pr[4] = pk2(f2.x, f2.y);
    pr[5] = pk2(f2.y, f3.x);
    pr[6] = pk2(f3.x, f3.y);
    pr[7] = pk2(f3.y, f4.x);
    pr[8] = pk2(f4.x, f4.y);
}

__global__ __launch_bounds__(256) void prop_kernel(int srcA, int mixidx) {
    __shared__ __align__(16) float sh[3][PTH + 6][PSW];
    const float* cur = srcA ? g_hnA : g_hnB;
    float* nxt = srcA ? g_hnB : g_hnA;

    int tid = threadIdx.x;
    int tx = tid & 15;
    int ty = tid >> 4;
    int bx = blockIdx.x;
    int by = blockIdx.y;
    int b  = blockIdx.z;
    int x0 = bx * PTW, y0 = by * PTH;

#pragma unroll
    for (int c = 0; c < 3; c++) {
        const float* plane = cur + (size_t)c * BHW + (size_t)b * HW;
        for (int i = tid; i < (PTH + 6) * 70; i += 256) {
            int r = i / 70, col = i - r * 70;
            int gy = y0 + r - 3, gx = x0 + col - 3;
            float v = 0.f;
            if (gy >= 0 && gy < Hh && gx >= 0 && gx < Ww) v = plane[gy * Ww + gx];
            sh[c][r][col] = v;
        }
    }
    __syncthreads();

    int xl = tx * 4;
    int p0 = (b * Hh + y0 + ty) * Ww + x0 + xl;

    uint64_t a3p0 = 0, a3p1 = 0, a5p0 = 0, a5p1 = 0, a7p0 = 0, a7p1 = 0;
    uint64_t pr[9];

#pragma unroll
    for (int ky = 0; ky < 3; ky++) {
        build_pr(&sh[0][ty + 2 + ky][xl], pr);
#pragma unroll
        for (int kx = 0; kx < 3; kx++) {
            const ulonglong2 wq = *(const ulonglong2*)&g_weights[(size_t)(0 + ky * 3 + kx) * BHW + p0];
            FMA2(a3p0, wq.x, pr[kx + 2], a3p0);
            FMA2(a3p1, wq.y, pr[kx + 4], a3p1);
        }
    }
#pragma unroll
    for (int ky = 0; ky < 5; ky++) {
        build_pr(&sh[1][ty + 1 + ky][xl], pr);
#pragma unroll
        for (int kx = 0; kx < 5; kx++) {
            const ulonglong2 wq = *(const ulonglong2*)&g_weights[(size_t)(9 + ky * 5 + kx) * BHW + p0];
            FMA2(a5p0, wq.x, pr[kx + 1], a5p0);
            FMA2(a5p1, wq.y, pr[kx + 3], a5p1);
        }
    }
#pragma unroll
    for (int ky = 0; ky < 7; ky++) {
        build_pr(&sh[2][ty + ky][xl], pr);
#pragma unroll
        for (int kx = 0; kx < 7; kx++) {
            const ulonglong2 wq = *(const ulonglong2*)&g_weights[(size_t)(34 + ky * 7 + kx) * BHW + p0];
            FMA2(a7p0, wq.x, pr[kx], a7p0);
            FMA2(a7p1, wq.y, pr[kx + 2], a7p1);
        }
    }

    *(uint64_t*)&nxt[p0]               = a3p0;
    *(uint64_t*)&nxt[p0 + 2]           = a3p1;
    *(uint64_t*)&nxt[BHW + p0]         = a5p0;
    *(uint64_t*)&nxt[BHW + p0 + 2]     = a5p1;
    *(uint64_t*)&nxt[2 * BHW + p0]     = a7p0;
    *(uint64_t*)&nxt[2 * BHW + p0 + 2] = a7p1;

    if (mixidx >= 0) {
        const ulonglong2 c3 = *(const ulonglong2*)&g_conf[p0];
        const ulonglong2 c5 = *(const ulonglong2*)&g_conf[BHW + p0];
        const ulonglong2 c7 = *(const ulonglong2*)&g_conf[2 * BHW + p0];
        uint64_t m0 = 0, m1 = 0;
        FMA2(m0, c3.x, a3p0, m0); FMA2(m0, c5.x, a5p0, m0); FMA2(m0, c7.x, a7p0, m0);
        FMA2(m1, c3.y, a3p1, m1); FMA2(m1, c5.y, a5p1, m1); FMA2(m1, c7.y, a7p1, m1);
        *(uint64_t*)&g_hns[(size_t)mixidx * BHW + p0]     = m0;
        *(uint64_t*)&g_hns[(size_t)mixidx * BHW + p0 + 2] = m1;
    }
}

// ---------------- K5: final conv(67ch,3x3) -> softmax -> blend ------------------
#define FTX 16
#define FTY 8
__global__ __launch_bounds__(128) void final_kernel(const float* __restrict__ fout,
                                                    const float* __restrict__ ctw,
                                                    const float* __restrict__ ctb,
                                                    float* __restrict__ out) {
    __shared__ float wct[3 * 67 * 9];
    __shared__ float tile[(FTY+2)*(FTX+2)];
    int tid = threadIdx.x;
    int tx = tid & (FTX-1);
    int ty = tid >> 4;
    int bidx = blockIdx.x;
    const int bw = Ww / FTX;
    const int bh = Hh / FTY;
    int bx = bidx % bw;
    int t2 = bidx / bw;
    int by = t2 % bh;
    int b  = t2 / bh;
    int x0 = bx * FTX, y0 = by * FTY;

    for (int i = tid; i < 3 * 67 * 9; i += 128) wct[i] = ctw[i];

    float acc0 = 0.f, acc1 = 0.f, acc2 = 0.f;
    for (int ic = 0; ic < 67; ic++) {
        const float* src = (ic < 64)
            ? fout + ((size_t)(b * Cc + ic)) * HW
            : g_hns + (size_t)(ic - 64) * BHW + (size_t)b * HW;
        __syncthreads();
        for (int i = tid; i < (FTY+2)*(FTX+2); i += 128) {
            int yy = i / (FTX+2), xx = i % (FTX+2);
            int gy = y0 + yy - 1, gx = x0 + xx - 1;
            float v = 0.f;
            if (gy >= 0 && gy < Hh && gx >= 0 && gx < Ww) v = src[gy * Ww + gx];
            tile[i] = v;
        }
        __syncthreads();
        float xv[9];
#pragma unroll
        for (int ky = 0; ky < 3; ky++)
#pragma unroll
            for (int kx = 0; kx < 3; kx++)
                xv[ky * 3 + kx] = tile[(ty + ky) * (FTX+2) + tx + kx];
#pragma unroll
        for (int k = 0; k < 9; k++) {
            acc0 = fmaf(wct[(0 * 67 + ic) * 9 + k], xv[k], acc0);
            acc1 = fmaf(wct[(1 * 67 + ic) * 9 + k], xv[k], acc1);
            acc2 = fmaf(wct[(2 * 67 + ic) * 9 + k], xv[k], acc2);
        }
    }

    int p = (b * Hh + y0 + ty) * Ww + x0 + tx;
    float l0 = acc0 + ctb[0];
    float l1 = acc1 + ctb[1];
    float l2 = acc2 + ctb[2];
    float m = fmaxf(l0, fmaxf(l1, l2));
    float e0 = __expf(l0 - m), e1 = __expf(l1 - m), e2 = __expf(l2 - m);
    float is = 1.f / (e0 + e1 + e2);
    float h0v = g_hns[p], h1v = g_hns[BHW + p], h2v = g_hns[2 * BHW + p];
    out[p] = (e0 * h0v + e1 * h1v + e2 * h2v) * is;
}

// ---------------- launch --------------------------------------------------------
extern "C" void kernel_launch(void* const* d_in, const int* in_sizes, int n_in,
                              void* d_out, int out_size) {
    const float* fout = (const float*)d_in[0];
    const float* hn   = (const float*)d_in[1];
    const float* w3c  = (const float*)d_in[3];
    const float* w3g  = (const float*)d_in[4];
    const float* w3b  = (const float*)d_in[5];
    const float* w5c  = (const float*)d_in[6];
    const float* w5g  = (const float*)d_in[7];
    const float* w5b  = (const float*)d_in[8];
    const float* w7c  = (const float*)d_in[9];
    const float* w7g  = (const float*)d_in[10];
    const float* w7b  = (const float*)d_in[11];
    const float* ckw  = (const float*)d_in[12];
    const float* ckb  = (const float*)d_in[13];
    const float* ctw  = (const float*)d_in[14];
    const float* ctb  = (const float*)d_in[15];
    const float* s3   = (const float*)d_in[16];
    const float* s5   = (const float*)d_in[17];
    const float* s7   = (const float*)d_in[18];
    float* out = (float*)d_out;

    {
        int n = 64 * NOCP * 9;
        reorg_kernel<<<(n + 255) / 256, 256>>>(w3c, w5c, w7c, ckw);
    }
    // keep profiled slot (4th launch) on conv83
    noop_kernel<<<1, 32>>>();
    noop_kernel<<<1, 32>>>();
    {
        dim3 g((Ww / CTILEW) * 3, Hh / CTY, Bb);   // 15 x 32 x 4
        conv83_kernel<<<g, 128>>>(fout);
    }
    {
        dim3 g(80, 64);
        stats_kernel<<<g, 256>>>();
    }
    finalize_kernel<<<1, 96>>>(w3g, w3b, w5g, w5b, w7g, w7b, ckb, s3, s5, s7);
    gen_weights_kernel<<<BHW / 512, 256>>>(hn);
    {
        dim3 g(Ww / PTW, Hh / PTH, Bb);
        prop_kernel<<<g, 256>>>(1, -1);
        prop_kernel<<<g, 256>>>(0, -1);
        prop_kernel<<<g, 256>>>(1,  1);
        prop_kernel<<<g, 256>>>(0, -1);
        prop_kernel<<<g, 256>>>(1, -1);
        prop_kernel<<<g, 256>>>(0,  2);
    }
    final_kernel<<<(Ww/FTX) * (Hh/FTY) * Bb, 128>>>(fout, ctw, ctb, out);
}

// round 5
// speedup vs baseline: 1.2348x; 1.0326x over previous
#include <cuda_runtime.h>
#include <cstdint>

#define Bb 4
#define Cc 64
#define Hh 256
#define Ww 320
#define HW (Hh*Ww)
#define BHW (Bb*HW)
#define NOC 83          // 8 (w3) + 24 (w5) + 48 (w7) + 3 (ck)
#define NOCP 84         // padded to 3 groups of 28
#define NWK 83
#define EPSW 1e-6f
#define BN_EPS 1e-5f

// ---------------- device scratch ------------------------------------------------
__device__ float g_wflat[64 * (NOCP*9)];
__device__ float g_convout[(size_t)NOCP * BHW];
__device__ float g_stats[2 * NOC];
__device__ float g_scale[NOC];
__device__ float g_shift[NOC];
__device__ float g_spatial[NWK];
__device__ float g_weights[(size_t)NWK * BHW];
__device__ float g_conf[3 * BHW];
__device__ float g_hnA[3 * BHW];
__device__ float g_hnB[3 * BHW];
__device__ float g_hns[3 * BHW];

// packed dual-fp32 FMA (sm_100+)
#define FMA2(d, a, b, c) \
    asm("fma.rn.f32x2 %0, %1, %2, %3;" : "=l"(d) : "l"(a), "l"(b), "l"(c))

__device__ __forceinline__ uint64_t pk2(float lo, float hi) {
    uint64_t r; asm("mov.b64 %0,{%1,%2};" : "=l"(r) : "f"(lo), "f"(hi)); return r;
}

__global__ void noop_kernel() {}

// ---------------- K0: reorder conv weights (pad oc 83 with zeros) --------------
__global__ void reorg_kernel(const float* __restrict__ w3, const float* __restrict__ w5,
                             const float* __restrict__ w7, const float* __restrict__ ck) {
    int i = blockIdx.x * blockDim.x + threadIdx.x;
    if (i < 2 * NOC) g_stats[i] = 0.f;
    if (i >= 64 * NOCP * 9) return;
    int k  = i % 9;
    int t  = i / 9;
    int oc = t % NOCP;
    int c  = t / NOCP;
    float v;
    if (oc < 8)        v = w3[(oc      * 64 + c) * 9 + k];
    else if (oc < 32)  v = w5[((oc-8)  * 64 + c) * 9 + k];
    else if (oc < 80)  v = w7[((oc-32) * 64 + c) * 9 + k];
    else if (oc < 83)  v = ck[((oc-80) * 64 + c) * 9 + k];
    else               v = 0.f;
    g_wflat[c * (NOCP*9) + oc * 9 + k] = v;
}

// ---------------- K1: 3x3 conv, 28 oc per block, 4 px per thread ----------------
#define CTY 8
#define CTILEW 64
#define CSTR 68          // smem row stride (66 used), 272B = 16B aligned
__global__ __launch_bounds__(128) void conv83_kernel(const float* __restrict__ fout) {
    __shared__ __align__(16) float wsm[28 * 12];
    __shared__ __align__(16) float tile[(CTY+2) * CSTR];

    int tid = threadIdx.x;
    int tx = tid & 15;           // 0..15, 4 px each
    int ty = tid >> 4;           // 0..7
    int gb = blockIdx.x;         // group fastest for L2 tile sharing
    int grp = gb % 3;
    int bx  = gb / 3;            // 0..4
    int by  = blockIdx.y;        // 0..31
    int b   = blockIdx.z;
    int x0 = bx * CTILEW, y0 = by * CTY;
    int ocbase = grp * 28;

    float4 acc[28];
#pragma unroll
    for (int i = 0; i < 28; i++) acc[i] = make_float4(0.f, 0.f, 0.f, 0.f);

    for (int c = 0; c < Cc; c++) {
        const float* src = fout + ((size_t)(b * Cc + c)) * HW;
        // input tile 10 x 66 (halo 1), zero-padded
        for (int i = tid; i < 10 * 66; i += 128) {
            int r = i / 66, col = i - r * 66;
            int gy = y0 + r - 1, gx = x0 + col - 1;
            float v = 0.f;
            if (gy >= 0 && gy < Hh && gx >= 0 && gx < Ww) v = src[gy * Ww + gx];
            tile[r * CSTR + col] = v;
        }
        // 28 x 9 weights for this channel/group
        const float* wsrc = g_wflat + c * (NOCP*9) + ocbase * 9;
        for (int i = tid; i < 28 * 9; i += 128) {
            int oc = i / 9, k = i - oc * 9;
            wsm[oc * 12 + k] = wsrc[i];
        }
        __syncthreads();

        // 3 rows x 6 input values per thread (4 px + 2 halo)
        float xv[3][6];
#pragma unroll
        for (int r = 0; r < 3; r++) {
            const float* row = &tile[(ty + r) * CSTR + tx * 4];
            float4 q = *(const float4*)row;
            float2 d = *(const float2*)(row + 4);
            xv[r][0] = q.x; xv[r][1] = q.y; xv[r][2] = q.z;
            xv[r][3] = q.w; xv[r][4] = d.x; xv[r][5] = d.y;
        }

#pragma unroll
        for (int oc = 0; oc < 28; oc++) {
            float4 wa = *(const float4*)&wsm[oc * 12];
            float4 wb = *(const float4*)&wsm[oc * 12 + 4];
            float  w8 = wsm[oc * 12 + 8];
            float w[9] = {wa.x, wa.y, wa.z, wa.w, wb.x, wb.y, wb.z, wb.w, w8};
            float4 a = acc[oc];
#pragma unroll
            for (int ky = 0; ky < 3; ky++) {
#pragma unroll
                for (int kx = 0; kx < 3; kx++) {
                    float wk = w[ky * 3 + kx];
                    a.x = fmaf(wk, xv[ky][0 + kx], a.x);
                    a.y = fmaf(wk, xv[ky][1 + kx], a.y);
                    a.z = fmaf(wk, xv[ky][2 + kx], a.z);
                    a.w = fmaf(wk, xv[ky][3 + kx], a.w);
                }
            }
            acc[oc] = a;
        }
        __syncthreads();
    }

    int p = (b * Hh + y0 + ty) * Ww + x0 + tx * 4;
#pragma unroll
    for (int oc = 0; oc < 28; oc++)
        *(float4*)&g_convout[(size_t)(ocbase + oc) * BHW + p] = acc[oc];
}

// ---------------- K2a: per-channel sum / sumsq ----------------------------------
__global__ void stats_kernel() {
    int oc = blockIdx.x;
    const int CHUNK = BHW / 64;
    const float* src = g_convout + (size_t)oc * BHW + blockIdx.y * CHUNK;
    float s = 0.f, s2 = 0.f;
    for (int i = threadIdx.x; i < CHUNK; i += 256) {
        float v = src[i];
        s += v;
        s2 = fmaf(v, v, s2);
    }
#pragma unroll
    for (int o = 16; o; o >>= 1) {
        s  += __shfl_down_sync(0xffffffffu, s,  o);
        s2 += __shfl_down_sync(0xffffffffu, s2, o);
    }
    __shared__ float sh[16];
    int w = threadIdx.x >> 5, l = threadIdx.x & 31;
    if (l == 0) { sh[w] = s; sh[8 + w] = s2; }
    __syncthreads();
    if (threadIdx.x == 0) {
        float a = 0.f, b2 = 0.f;
        for (int i = 0; i < 8; i++) { a += sh[i]; b2 += sh[8 + i]; }
        atomicAdd(&g_stats[oc], a);
        atomicAdd(&g_stats[NOC + oc], b2);
    }
}

// ---------------- K2b: finalize BN affine + spatial table -----------------------
__global__ void finalize_kernel(const float* __restrict__ w3g, const float* __restrict__ w3b,
                                const float* __restrict__ w5g, const float* __restrict__ w5b,
                                const float* __restrict__ w7g, const float* __restrict__ w7b,
                                const float* __restrict__ ckb,
                                const float* __restrict__ ps3,
                                const float* __restrict__ ps5,
                                const float* __restrict__ ps7) {
    int oc = threadIdx.x;
    if (oc < NWK) {
        int pk, kk, kb;
        float sig;
        if (oc < 9)       { pk = 3; kb = 0;  sig = *ps3; }
        else if (oc < 34) { pk = 5; kb = 9;  sig = *ps5; }
        else              { pk = 7; kb = 34; sig = *ps7; }
        kk = oc - kb;
        int ki = kk / pk, kj = kk % pk;
        float ri = -1.f + 2.f * (float)ki / (float)(pk - 1);
        float rj = -1.f + 2.f * (float)kj / (float)(pk - 1);
        g_spatial[oc] = __expf(-(ri * ri + rj * rj) / (2.f * sig * sig));
    }
    if (oc >= NOC) return;
    if (oc < 80) {
        float N = (float)BHW;
        float mean = g_stats[oc] / N;
        float var  = g_stats[NOC + oc] / N - mean * mean;
        float inv  = rsqrtf(var + BN_EPS);
        float g, bb;
        if (oc < 8)       { g = w3g[oc];      bb = w3b[oc]; }
        else if (oc < 32) { g = w5g[oc - 8];  bb = w5b[oc - 8]; }
        else              { g = w7g[oc - 32]; bb = w7b[oc - 32]; }
        g_scale[oc] = g * inv;
        g_shift[oc] = bb - mean * g * inv;
    } else {
        g_scale[oc] = 1.f;
        g_shift[oc] = ckb[oc - 80];
    }
}

// ---------------- K3: per-pixel kernel generation (2 px/thread) -----------------
template <int NC, int PK>
__device__ __forceinline__ void gen_group2(int p, int ocbase, int kbase, const float* __restrict__ sp) {
    const int KK = PK * PK;
    float w0[NC], w1[NC];
    float s0 = 0.f, s1 = 0.f;
#pragma unroll
    for (int j = 0; j < NC; j++) {
        float2 x = *(const float2*)&g_convout[(size_t)(ocbase + j) * BHW + p];
        float sc = g_scale[ocbase + j], sh = g_shift[ocbase + j];
        float a = fmaxf(fmaf(sc, x.x, sh), 0.f);
        float b = fmaxf(fmaf(sc, x.y, sh), 0.f);
        w0[j] = a; w1[j] = b;
        s0 += a;  s1 += b;
    }
    float i0 = 1.f / (s0 + EPSW), i1 = 1.f / (s1 + EPSW);
    float mid0 = 1.f - s0 * i0,   mid1 = 1.f - s1 * i1;
    const int h = (KK - 1) / 2;
    float f0[KK], f1[KK];
#pragma unroll
    for (int j = 0; j < h; j++) { f0[j] = w0[j] * i0; f1[j] = w1[j] * i1; }
    f0[h] = mid0; f1[h] = mid1;
#pragma unroll
    for (int j = 0; j < NC - h; j++) { f0[h+1+j] = w0[h+j] * i0; f1[h+1+j] = w1[h+j] * i1; }

    float t0 = 0.f, t1 = 0.f;
#pragma unroll
    for (int k = 0; k < KK; k++) {
        float sk = sp[kbase + k];
        f0[k] *= sk; f1[k] *= sk;
        t0 += f0[k]; t1 += f1[k];
    }
    float it0 = 1.f / fmaxf(t0, 1e-7f);
    float it1 = 1.f / fmaxf(t1, 1e-7f);
#pragma unroll
    for (int k = 0; k < KK; k++) {
        float2 o; o.x = f0[k] * it0; o.y = f1[k] * it1;
        *(float2*)&g_weights[(size_t)(kbase + k) * BHW + p] = o;
    }
}

__global__ __launch_bounds__(256) void gen_weights_kernel(const float* __restrict__ hn) {
    __shared__ float ssp[NWK];
    int tid = threadIdx.x;
    if (tid < NWK) ssp[tid] = g_spatial[tid];
    __syncthreads();
    int p = 2 * (blockIdx.x * 256 + tid);
    if (p >= BHW) return;
    gen_group2<8, 3>(p, 0, 0, ssp);
    gen_group2<24, 5>(p, 8, 9, ssp);
    gen_group2<48, 7>(p, 32, 34, ssp);

    float2 l0 = *(const float2*)&g_convout[(size_t)80 * BHW + p];
    float2 l1 = *(const float2*)&g_convout[(size_t)81 * BHW + p];
    float2 l2 = *(const float2*)&g_convout[(size_t)82 * BHW + p];
    float s80 = g_shift[80], s81 = g_shift[81], s82 = g_shift[82];
#pragma unroll
    for (int hfi = 0; hfi < 2; hfi++) {
        float a = (hfi ? l0.y : l0.x) + s80;
        float b = (hfi ? l1.y : l1.x) + s81;
        float c = (hfi ? l2.y : l2.x) + s82;
        float m = fmaxf(a, fmaxf(b, c));
        float e0 = __expf(a - m), e1 = __expf(b - m), e2 = __expf(c - m);
        float is = 1.f / (e0 + e1 + e2);
        g_conf[p + hfi] = e0 * is;
        g_conf[BHW + p + hfi] = e1 * is;
        g_conf[2 * BHW + p + hfi] = e2 * is;
    }
    float2 hv = *(const float2*)&hn[p];
    *(float2*)&g_hnA[p] = hv;
    *(float2*)&g_hnA[BHW + p] = hv;
    *(float2*)&g_hnA[2 * BHW + p] = hv;
    *(float2*)&g_hns[p] = hv;
}

// ---------------- K4: propagation, smem-tiled, 4 px/thread, FFMA2 ---------------
#define PTW 64
#define PTH 16
#define PSW 72
__device__ __forceinline__ void build_pr(const float* __restrict__ rowp, uint64_t pr[9]) {
    float2 f0 = *(const float2*)(rowp);
    float2 f1 = *(const float2*)(rowp + 2);
    float2 f2 = *(const float2*)(rowp + 4);
    float2 f3 = *(const float2*)(rowp + 6);
    float2 f4 = *(const float2*)(rowp + 8);
    pr[0] = pk2(f0.x, f0.y);
    pr[1] = pk2(f0.y, f1.x);
    pr[2] = pk2(f1.x, f1.y);
    pr[3] = pk2(f1.y, f2.x);
    pr[4] = pk2(f2.x, f2.y);
    pr[5] = pk2(f2.y, f3.x);
    pr[6] = pk2(f3.x, f3.y);
    pr[7] = pk2(f3.y, f4.x);
    pr[8] = pk2(f4.x, f4.y);
}

__global__ __launch_bounds__(256) void prop_kernel(int srcA, int mixidx) {
    __shared__ __align__(16) float sh[3][PTH + 6][PSW];
    const float* cur = srcA ? g_hnA : g_hnB;
    float* nxt = srcA ? g_hnB : g_hnA;

    int tid = threadIdx.x;
    int tx = tid & 15;
    int ty = tid >> 4;
    int bx = blockIdx.x;
    int by = blockIdx.y;
    int b  = blockIdx.z;
    int x0 = bx * PTW, y0 = by * PTH;

#pragma unroll
    for (int c = 0; c < 3; c++) {
        const float* plane = cur + (size_t)c * BHW + (size_t)b * HW;
        for (int i = tid; i < (PTH + 6) * 70; i += 256) {
            int r = i / 70, col = i - r * 70;
            int gy = y0 + r - 3, gx = x0 + col - 3;
            float v = 0.f;
            if (gy >= 0 && gy < Hh && gx >= 0 && gx < Ww) v = plane[gy * Ww + gx];
            sh[c][r][col] = v;
        }
    }
    __syncthreads();

    int xl = tx * 4;
    int p0 = (b * Hh + y0 + ty) * Ww + x0 + xl;

    uint64_t a3p0 = 0, a3p1 = 0, a5p0 = 0, a5p1 = 0, a7p0 = 0, a7p1 = 0;
    uint64_t pr[9];

#pragma unroll
    for (int ky = 0; ky < 3; ky++) {
        build_pr(&sh[0][ty + 2 + ky][xl], pr);
#pragma unroll
        for (int kx = 0; kx < 3; kx++) {
            const ulonglong2 wq = *(const ulonglong2*)&g_weights[(size_t)(0 + ky * 3 + kx) * BHW + p0];
            FMA2(a3p0, wq.x, pr[kx + 2], a3p0);
            FMA2(a3p1, wq.y, pr[kx + 4], a3p1);
        }
    }
#pragma unroll
    for (int ky = 0; ky < 5; ky++) {
        build_pr(&sh[1][ty + 1 + ky][xl], pr);
#pragma unroll
        for (int kx = 0; kx < 5; kx++) {
            const ulonglong2 wq = *(const ulonglong2*)&g_weights[(size_t)(9 + ky * 5 + kx) * BHW + p0];
            FMA2(a5p0, wq.x, pr[kx + 1], a5p0);
            FMA2(a5p1, wq.y, pr[kx + 3], a5p1);
        }
    }
#pragma unroll
    for (int ky = 0; ky < 7; ky++) {
        build_pr(&sh[2][ty + ky][xl], pr);
#pragma unroll
        for (int kx = 0; kx < 7; kx++) {
            const ulonglong2 wq = *(const ulonglong2*)&g_weights[(size_t)(34 + ky * 7 + kx) * BHW + p0];
            FMA2(a7p0, wq.x, pr[kx], a7p0);
            FMA2(a7p1, wq.y, pr[kx + 2], a7p1);
        }
    }

    *(uint64_t*)&nxt[p0]               = a3p0;
    *(uint64_t*)&nxt[p0 + 2]           = a3p1;
    *(uint64_t*)&nxt[BHW + p0]         = a5p0;
    *(uint64_t*)&nxt[BHW + p0 + 2]     = a5p1;
    *(uint64_t*)&nxt[2 * BHW + p0]     = a7p0;
    *(uint64_t*)&nxt[2 * BHW + p0 + 2] = a7p1;

    if (mixidx >= 0) {
        const ulonglong2 c3 = *(const ulonglong2*)&g_conf[p0];
        const ulonglong2 c5 = *(const ulonglong2*)&g_conf[BHW + p0];
        const ulonglong2 c7 = *(const ulonglong2*)&g_conf[2 * BHW + p0];
        uint64_t m0 = 0, m1 = 0;
        FMA2(m0, c3.x, a3p0, m0); FMA2(m0, c5.x, a5p0, m0); FMA2(m0, c7.x, a7p0, m0);
        FMA2(m1, c3.y, a3p1, m1); FMA2(m1, c5.y, a5p1, m1); FMA2(m1, c7.y, a7p1, m1);
        *(uint64_t*)&g_hns[(size_t)mixidx * BHW + p0]     = m0;
        *(uint64_t*)&g_hns[(size_t)mixidx * BHW + p0 + 2] = m1;
    }
}

// ---------------- K5: final conv(67ch,3x3) -> softmax -> blend ------------------
#define FTX 16
#define FTY 8
__global__ __launch_bounds__(128) void final_kernel(const float* __restrict__ fout,
                                                    const float* __restrict__ ctw,
                                                    const float* __restrict__ ctb,
                                                    float* __restrict__ out) {
    __shared__ float wct[3 * 67 * 9];
    __shared__ float tile[(FTY+2)*(FTX+2)];
    int tid = threadIdx.x;
    int tx = tid & (FTX-1);
    int ty = tid >> 4;
    int bidx = blockIdx.x;
    const int bw = Ww / FTX;
    const int bh = Hh / FTY;
    int bx = bidx % bw;
    int t2 = bidx / bw;
    int by = t2 % bh;
    int b  = t2 / bh;
    int x0 = bx * FTX, y0 = by * FTY;

    for (int i = tid; i < 3 * 67 * 9; i += 128) wct[i] = ctw[i];

    float acc0 = 0.f, acc1 = 0.f, acc2 = 0.f;
    for (int ic = 0; ic < 67; ic++) {
        const float* src = (ic < 64)
            ? fout + ((size_t)(b * Cc + ic)) * HW
            : g_hns + (size_t)(ic - 64) * BHW + (size_t)b * HW;
        __syncthreads();
        for (int i = tid; i < (FTY+2)*(FTX+2); i += 128) {
            int yy = i / (FTX+2), xx = i % (FTX+2);
            int gy = y0 + yy - 1, gx = x0 + xx - 1;
            float v = 0.f;
            if (gy >= 0 && gy < Hh && gx >= 0 && gx < Ww) v = src[gy * Ww + gx];
            tile[i] = v;
        }
        __syncthreads();
        float xv[9];
#pragma unroll
        for (int ky = 0; ky < 3; ky++)
#pragma unroll
            for (int kx = 0; kx < 3; kx++)
                xv[ky * 3 + kx] = tile[(ty + ky) * (FTX+2) + tx + kx];
#pragma unroll
        for (int k = 0; k < 9; k++) {
            acc0 = fmaf(wct[(0 * 67 + ic) * 9 + k], xv[k], acc0);
            acc1 = fmaf(wct[(1 * 67 + ic) * 9 + k], xv[k], acc1);
            acc2 = fmaf(wct[(2 * 67 + ic) * 9 + k], xv[k], acc2);
        }
    }

    int p = (b * Hh + y0 + ty) * Ww + x0 + tx;
    float l0 = acc0 + ctb[0];
    float l1 = acc1 + ctb[1];
    float l2 = acc2 + ctb[2];
    float m = fmaxf(l0, fmaxf(l1, l2));
    float e0 = __expf(l0 - m), e1 = __expf(l1 - m), e2 = __expf(l2 - m);
    float is = 1.f / (e0 + e1 + e2);
    float h0v = g_hns[p], h1v = g_hns[BHW + p], h2v = g_hns[2 * BHW + p];
    out[p] = (e0 * h0v + e1 * h1v + e2 * h2v) * is;
}

// ---------------- launch --------------------------------------------------------
extern "C" void kernel_launch(void* const* d_in, const int* in_sizes, int n_in,
                              void* d_out, int out_size) {
    const float* fout = (const float*)d_in[0];
    const float* hn   = (const float*)d_in[1];
    const float* w3c  = (const float*)d_in[3];
    const float* w3g  = (const float*)d_in[4];
    const float* w3b  = (const float*)d_in[5];
    const float* w5c  = (const float*)d_in[6];
    const float* w5g  = (const float*)d_in[7];
    const float* w5b  = (const float*)d_in[8];
    const float* w7c  = (const float*)d_in[9];
    const float* w7g  = (const float*)d_in[10];
    const float* w7b  = (const float*)d_in[11];
    const float* ckw  = (const float*)d_in[12];
    const float* ckb  = (const float*)d_in[13];
    const float* ctw  = (const float*)d_in[14];
    const float* ctb  = (const float*)d_in[15];
    const float* s3   = (const float*)d_in[16];
    const float* s5   = (const float*)d_in[17];
    const float* s7   = (const float*)d_in[18];
    float* out = (float*)d_out;

    {
        int n = 64 * NOCP * 9;
        reorg_kernel<<<(n + 255) / 256, 256>>>(w3c, w5c, w7c, ckw);
    }
    // keep profiled slot (4th launch) on conv83
    noop_kernel<<<1, 32>>>();
    noop_kernel<<<1, 32>>>();
    {
        dim3 g((Ww / CTILEW) * 3, Hh / CTY, Bb);   // 15 x 32 x 4
        conv83_kernel<<<g, 128>>>(fout);
    }
    {
        dim3 g(80, 64);
        stats_kernel<<<g, 256>>>();
    }
    finalize_kernel<<<1, 96>>>(w3g, w3b, w5g, w5b, w7g, w7b, ckb, s3, s5, s7);
    gen_weights_kernel<<<BHW / 512, 256>>>(hn);
    {
        dim3 g(Ww / PTW, Hh / PTH, Bb);
        prop_kernel<<<g, 256>>>(1, -1);
        prop_kernel<<<g, 256>>>(0, -1);
        prop_kernel<<<g, 256>>>(1,  1);
        prop_kernel<<<g, 256>>>(0, -1);
        prop_kernel<<<g, 256>>>(1, -1);
        prop_kernel<<<g, 256>>>(0,  2);
    }
    final_kernel<<<(Ww/FTX) * (Hh/FTY) * Bb, 128>>>(fout, ctw, ctb, out);
}

// round 7
// speedup vs baseline: 1.4255x; 1.1545x over previous
#include <cuda_runtime.h>
#include <cstdint>

#define Bb 4
#define Cc 64
#define Hh 256
#define Ww 320
#define HW (Hh*Ww)
#define BHW (Bb*HW)
#define NOC 83          // 8 (w3) + 24 (w5) + 48 (w7) + 3 (ck)
#define NOCP 84         // padded to 6 groups of 14
#define NWK 83
#define EPSW 1e-6f
#define BN_EPS 1e-5f

// ---------------- device scratch ------------------------------------------------
__device__ float g_wflat[64 * (NOCP*9)];
__device__ float g_convout[(size_t)NOCP * BHW];
__device__ float g_stats[2 * NOC];
__device__ float g_scale[NOC];
__device__ float g_shift[NOC];
__device__ float g_spatial[NWK];
__device__ float g_weights[(size_t)NWK * BHW];
__device__ float g_conf[3 * BHW];
__device__ float g_hnA[3 * BHW];
__device__ float g_hnB[3 * BHW];
__device__ float g_hns[3 * BHW];

// packed dual-fp32 FMA (sm_100+)
#define FMA2(d, a, b, c) \
    asm("fma.rn.f32x2 %0, %1, %2, %3;" : "=l"(d) : "l"(a), "l"(b), "l"(c))

__device__ __forceinline__ uint64_t pk2(float lo, float hi) {
    uint64_t r; asm("mov.b64 %0,{%1,%2};" : "=l"(r) : "f"(lo), "f"(hi)); return r;
}

__global__ void noop_kernel() {}

// ---------------- K0: reorder conv weights (pad oc 83 with zeros) --------------
__global__ void reorg_kernel(const float* __restrict__ w3, const float* __restrict__ w5,
                             const float* __restrict__ w7, const float* __restrict__ ck) {
    int i = blockIdx.x * blockDim.x + threadIdx.x;
    if (i < 2 * NOC) g_stats[i] = 0.f;
    if (i >= 64 * NOCP * 9) return;
    int k  = i % 9;
    int t  = i / 9;
    int oc = t % NOCP;
    int c  = t / NOCP;
    float v;
    if (oc < 8)        v = w3[(oc      * 64 + c) * 9 + k];
    else if (oc < 32)  v = w5[((oc-8)  * 64 + c) * 9 + k];
    else if (oc < 80)  v = w7[((oc-32) * 64 + c) * 9 + k];
    else if (oc < 83)  v = ck[((oc-80) * 64 + c) * 9 + k];
    else               v = 0.f;
    g_wflat[c * (NOCP*9) + oc * 9 + k] = v;
}

// ---------------- K1: 3x3 conv, FFMA2, 14 oc/block, 4 px/thread, 2ch/phase -----
#define CTY 8
#define CTILEW 64
#define CSTR 68          // smem row stride floats (66 used)
__global__ __launch_bounds__(128, 3) void conv83_kernel(const float* __restrict__ fout) {
    __shared__ __align__(16) float tile[2][10 * CSTR];
    __shared__ __align__(16) float wsm[2][14 * 20];   // weights splatted to pairs

    int tid = threadIdx.x;
    int tx = tid & 15;           // 0..15, 4 px each
    int ty = tid >> 4;           // 0..7
    int gb = blockIdx.x;
    int grp = gb % 6;            // group fastest -> shared tile in L2
    int bx  = gb / 6;            // 0..4
    int by  = blockIdx.y;        // 0..31
    int b   = blockIdx.z;
    int x0 = bx * CTILEW, y0 = by * CTY;
    int ocbase = grp * 14;

    uint64_t acc[28];            // 14 oc x 2 pixel-pairs
#pragma unroll
    for (int i = 0; i < 28; i++) acc[i] = 0ull;

    for (int c0 = 0; c0 < Cc; c0 += 2) {
        // load 2 channel tiles (10 x 66, halo 1, zero-padded)
#pragma unroll
        for (int cc = 0; cc < 2; cc++) {
            const float* src = fout + ((size_t)(b * Cc + c0 + cc)) * HW;
            for (int i = tid; i < 10 * 66; i += 128) {
                int r = i / 66, col = i - r * 66;
                int gy = y0 + r - 1, gx = x0 + col - 1;
                float v = 0.f;
                if (gy >= 0 && gy < Hh && gx >= 0 && gx < Ww) v = src[gy * Ww + gx];
                tile[cc][r * CSTR + col] = v;
            }
        }
        // load + splat weights for both channels
        for (int i = tid; i < 2 * 14 * 9; i += 128) {
            int cc = i / 126;
            int r  = i - cc * 126;
            int oc = r / 9, k = r - oc * 9;
            float w = g_wflat[(size_t)(c0 + cc) * (NOCP*9) + (ocbase + oc) * 9 + k];
            wsm[cc][oc * 20 + 2*k]     = w;
            wsm[cc][oc * 20 + 2*k + 1] = w;
        }
        __syncthreads();

#pragma unroll
        for (int cc = 0; cc < 2; cc++) {
            // per row: 6 values v[0..5] -> 5 packed pairs pr[j]=(v[j],v[j+1])
            uint64_t pr[3][5];
#pragma unroll
            for (int r = 0; r < 3; r++) {
                const float* row = &tile[cc][(ty + r) * CSTR + tx * 4];
                float4 q = *(const float4*)row;
                float2 d = *(const float2*)(row + 4);
                pr[r][0] = pk2(q.x, q.y);
                pr[r][1] = pk2(q.y, q.z);
                pr[r][2] = pk2(q.z, q.w);
                pr[r][3] = pk2(q.w, d.x);
                pr[r][4] = pk2(d.x, d.y);
            }
            const ulonglong2* wq = (const ulonglong2*)wsm[cc];
#pragma unroll
            for (int oc = 0; oc < 14; oc++) {
                ulonglong2 w01 = wq[oc * 5 + 0];
                ulonglong2 w23 = wq[oc * 5 + 1];
                ulonglong2 w45 = wq[oc * 5 + 2];
                ulonglong2 w67 = wq[oc * 5 + 3];
                uint64_t   w8  = ((const uint64_t*)wsm[cc])[oc * 10 + 8];
                uint64_t w[9] = {w01.x, w01.y, w23.x, w23.y, w45.x, w45.y, w67.x, w67.y, w8};
                uint64_t a0 = acc[oc * 2], a1 = acc[oc * 2 + 1];
#pragma unroll
                for (int ky = 0; ky < 3; ky++) {
#pragma unroll
                    for (int kx = 0; kx < 3; kx++) {
                        uint64_t wk = w[ky * 3 + kx];
                        FMA2(a0, wk, pr[ky][kx],     a0);
                        FMA2(a1, wk, pr[ky][kx + 2], a1);
                    }
                }
                acc[oc * 2] = a0; acc[oc * 2 + 1] = a1;
            }
        }
        __syncthreads();
    }

    int p = (b * Hh + y0 + ty) * Ww + x0 + tx * 4;
#pragma unroll
    for (int oc = 0; oc < 14; oc++) {
        ulonglong2 st; st.x = acc[oc * 2]; st.y = acc[oc * 2 + 1];
        *(ulonglong2*)&g_convout[(size_t)(ocbase + oc) * BHW + p] = st;
    }
}

// ---------------- K2a: per-channel sum / sumsq ----------------------------------
__global__ void stats_kernel() {
    int oc = blockIdx.x;
    const int CHUNK = BHW / 64;
    const float* src = g_convout + (size_t)oc * BHW + blockIdx.y * CHUNK;
    float s = 0.f, s2 = 0.f;
    for (int i = threadIdx.x; i < CHUNK; i += 256) {
        float v = src[i];
        s += v;
        s2 = fmaf(v, v, s2);
    }
#pragma unroll
    for (int o = 16; o; o >>= 1) {
        s  += __shfl_down_sync(0xffffffffu, s,  o);
        s2 += __shfl_down_sync(0xffffffffu, s2, o);
    }
    __shared__ float sh[16];
    int w = threadIdx.x >> 5, l = threadIdx.x & 31;
    if (l == 0) { sh[w] = s; sh[8 + w] = s2; }
    __syncthreads();
    if (threadIdx.x == 0) {
        float a = 0.f, b2 = 0.f;
        for (int i = 0; i < 8; i++) { a += sh[i]; b2 += sh[8 + i]; }
        atomicAdd(&g_stats[oc], a);
        atomicAdd(&g_stats[NOC + oc], b2);
    }
}

// ---------------- K2b: finalize BN affine + spatial table -----------------------
__global__ void finalize_kernel(const float* __restrict__ w3g, const float* __restrict__ w3b,
                                const float* __restrict__ w5g, const float* __restrict__ w5b,
                                const float* __restrict__ w7g, const float* __restrict__ w7b,
                                const float* __restrict__ ckb,
                                const float* __restrict__ ps3,
                                const float* __restrict__ ps5,
                                const float* __restrict__ ps7) {
    int oc = threadIdx.x;
    if (oc < NWK) {
        int pk, kk, kb;
        float sig;
        if (oc < 9)       { pk = 3; kb = 0;  sig = *ps3; }
        else if (oc < 34) { pk = 5; kb = 9;  sig = *ps5; }
        else              { pk = 7; kb = 34; sig = *ps7; }
        kk = oc - kb;
        int ki = kk / pk, kj = kk % pk;
        float ri = -1.f + 2.f * (float)ki / (float)(pk - 1);
        float rj = -1.f + 2.f * (float)kj / (float)(pk - 1);
        g_spatial[oc] = __expf(-(ri * ri + rj * rj) / (2.f * sig * sig));
    }
    if (oc >= NOC) return;
    if (oc < 80) {
        float N = (float)BHW;
        float mean = g_stats[oc] / N;
        float var  = g_stats[NOC + oc] / N - mean * mean;
        float inv  = rsqrtf(var + BN_EPS);
        float g, bb;
        if (oc < 8)       { g = w3g[oc];      bb = w3b[oc]; }
        else if (oc < 32) { g = w5g[oc - 8];  bb = w5b[oc - 8]; }
        else              { g = w7g[oc - 32]; bb = w7b[oc - 32]; }
        g_scale[oc] = g * inv;
        g_shift[oc] = bb - mean * g * inv;
    } else {
        g_scale[oc] = 1.f;
        g_shift[oc] = ckb[oc - 80];
    }
}

// ---------------- K3: per-pixel kernel generation (2 px/thread) -----------------
template <int NC, int PK>
__device__ __forceinline__ void gen_group2(int p, int ocbase, int kbase, const float* __restrict__ sp) {
    const int KK = PK * PK;
    float w0[NC], w1[NC];
    float s0 = 0.f, s1 = 0.f;
#pragma unroll
    for (int j = 0; j < NC; j++) {
        float2 x = *(const float2*)&g_convout[(size_t)(ocbase + j) * BHW + p];
        float sc = g_scale[ocbase + j], sh = g_shift[ocbase + j];
        float a = fmaxf(fmaf(sc, x.x, sh), 0.f);
        float b = fmaxf(fmaf(sc, x.y, sh), 0.f);
        w0[j] = a; w1[j] = b;
        s0 += a;  s1 += b;
    }
    float i0 = 1.f / (s0 + EPSW), i1 = 1.f / (s1 + EPSW);
    float mid0 = 1.f - s0 * i0,   mid1 = 1.f - s1 * i1;
    const int h = (KK - 1) / 2;
    float f0[KK], f1[KK];
#pragma unroll
    for (int j = 0; j < h; j++) { f0[j] = w0[j] * i0; f1[j] = w1[j] * i1; }
    f0[h] = mid0; f1[h] = mid1;
#pragma unroll
    for (int j = 0; j < NC - h; j++) { f0[h+1+j] = w0[h+j] * i0; f1[h+1+j] = w1[h+j] * i1; }

    float t0 = 0.f, t1 = 0.f;
#pragma unroll
    for (int k = 0; k < KK; k++) {
        float sk = sp[kbase + k];
        f0[k] *= sk; f1[k] *= sk;
        t0 += f0[k]; t1 += f1[k];
    }
    float it0 = 1.f / fmaxf(t0, 1e-7f);
    float it1 = 1.f / fmaxf(t1, 1e-7f);
#pragma unroll
    for (int k = 0; k < KK; k++) {
        float2 o; o.x = f0[k] * it0; o.y = f1[k] * it1;
        *(float2*)&g_weights[(size_t)(kbase + k) * BHW + p] = o;
    }
}

__global__ __launch_bounds__(256) void gen_weights_kernel(const float* __restrict__ hn) {
    __shared__ float ssp[NWK];
    int tid = threadIdx.x;
    if (tid < NWK) ssp[tid] = g_spatial[tid];
    __syncthreads();
    int p = 2 * (blockIdx.x * 256 + tid);
    if (p >= BHW) return;
    gen_group2<8, 3>(p, 0, 0, ssp);
    gen_group2<24, 5>(p, 8, 9, ssp);
    gen_group2<48, 7>(p, 32, 34, ssp);

    float2 l0 = *(const float2*)&g_convout[(size_t)80 * BHW + p];
    float2 l1 = *(const float2*)&g_convout[(size_t)81 * BHW + p];
    float2 l2 = *(const float2*)&g_convout[(size_t)82 * BHW + p];
    float s80 = g_shift[80], s81 = g_shift[81], s82 = g_shift[82];
#pragma unroll
    for (int hfi = 0; hfi < 2; hfi++) {
        float a = (hfi ? l0.y : l0.x) + s80;
        float b = (hfi ? l1.y : l1.x) + s81;
        float c = (hfi ? l2.y : l2.x) + s82;
        float m = fmaxf(a, fmaxf(b, c));
        float e0 = __expf(a - m), e1 = __expf(b - m), e2 = __expf(c - m);
        float is = 1.f / (e0 + e1 + e2);
        g_conf[p + hfi] = e0 * is;
        g_conf[BHW + p + hfi] = e1 * is;
        g_conf[2 * BHW + p + hfi] = e2 * is;
    }
    float2 hv = *(const float2*)&hn[p];
    *(float2*)&g_hnA[p] = hv;
    *(float2*)&g_hnA[BHW + p] = hv;
    *(float2*)&g_hnA[2 * BHW + p] = hv;
    *(float2*)&g_hns[p] = hv;
}

// ---------------- K4: propagation, smem-tiled, 4 px/thread, FFMA2 ---------------
#define PTW 64
#define PTH 16
#define PSW 72
__device__ __forceinline__ void build_pr(const float* __restrict__ rowp, uint64_t pr[9]) {
    float2 f0 = *(const float2*)(rowp);
    float2 f1 = *(const float2*)(rowp + 2);
    float2 f2 = *(const float2*)(rowp + 4);
    float2 f3 = *(const float2*)(rowp + 6);
    float2 f4 = *(const float2*)(rowp + 8);
    pr[0] = pk2(f0.x, f0.y);
    pr[1] = pk2(f0.y, f1.x);
    pr[2] = pk2(f1.x, f1.y);
    pr[3] = pk2(f1.y, f2.x);
    pr[4] = pk2(f2.x, f2.y);
    pr[5] = pk2(f2.y, f3.x);
    pr[6] = pk2(f3.x, f3.y);
    pr[7] = pk2(f3.y, f4.x);
    pr[8] = pk2(f4.x, f4.y);
}

__global__ __launch_bounds__(256) void prop_kernel(int srcA, int mixidx) {
    __shared__ __align__(16) float sh[3][PTH + 6][PSW];
    const float* cur = srcA ? g_hnA : g_hnB;
    float* nxt = srcA ? g_hnB : g_hnA;

    int tid = threadIdx.x;
    int tx = tid & 15;
    int ty = tid >> 4;
    int bx = blockIdx.x;
    int by = blockIdx.y;
    int b  = blockIdx.z;
    int x0 = bx * PTW, y0 = by * PTH;

#pragma unroll
    for (int c = 0; c < 3; c++) {
        const float* plane = cur + (size_t)c * BHW + (size_t)b * HW;
        for (int i = tid; i < (PTH + 6) * 70; i += 256) {
            int r = i / 70, col = i - r * 70;
            int gy = y0 + r - 3, gx = x0 + col - 3;
            float v = 0.f;
            if (gy >= 0 && gy < Hh && gx >= 0 && gx < Ww) v = plane[gy * Ww + gx];
            sh[c][r][col] = v;
        }
    }
    __syncthreads();

    int xl = tx * 4;
    int p0 = (b * Hh + y0 + ty) * Ww + x0 + xl;

    uint64_t a3p0 = 0, a3p1 = 0, a5p0 = 0, a5p1 = 0, a7p0 = 0, a7p1 = 0;
    uint64_t pr[9];

#pragma unroll
    for (int ky = 0; ky < 3; ky++) {
        build_pr(&sh[0][ty + 2 + ky][xl], pr);
#pragma unroll
        for (int kx = 0; kx < 3; kx++) {
            const ulonglong2 wq = *(const ulonglong2*)&g_weights[(size_t)(0 + ky * 3 + kx) * BHW + p0];
            FMA2(a3p0, wq.x, pr[kx + 2], a3p0);
            FMA2(a3p1, wq.y, pr[kx + 4], a3p1);
        }
    }
#pragma unroll
    for (int ky = 0; ky < 5; ky++) {
        build_pr(&sh[1][ty + 1 + ky][xl], pr);
#pragma unroll
        for (int kx = 0; kx < 5; kx++) {
            const ulonglong2 wq = *(const ulonglong2*)&g_weights[(size_t)(9 + ky * 5 + kx) * BHW + p0];
            FMA2(a5p0, wq.x, pr[kx + 1], a5p0);
            FMA2(a5p1, wq.y, pr[kx + 3], a5p1);
        }
    }
#pragma unroll
    for (int ky = 0; ky < 7; ky++) {
        build_pr(&sh[2][ty + ky][xl], pr);
#pragma unroll
        for (int kx = 0; kx < 7; kx++) {
            const ulonglong2 wq = *(const ulonglong2*)&g_weights[(size_t)(34 + ky * 7 + kx) * BHW + p0];
            FMA2(a7p0, wq.x, pr[kx], a7p0);
            FMA2(a7p1, wq.y, pr[kx + 2], a7p1);
        }
    }

    *(uint64_t*)&nxt[p0]               = a3p0;
    *(uint64_t*)&nxt[p0 + 2]           = a3p1;
    *(uint64_t*)&nxt[BHW + p0]         = a5p0;
    *(uint64_t*)&nxt[BHW + p0 + 2]     = a5p1;
    *(uint64_t*)&nxt[2 * BHW + p0]     = a7p0;
    *(uint64_t*)&nxt[2 * BHW + p0 + 2] = a7p1;

    if (mixidx >= 0) {
        const ulonglong2 c3 = *(const ulonglong2*)&g_conf[p0];
        const ulonglong2 c5 = *(const ulonglong2*)&g_conf[BHW + p0];
        const ulonglong2 c7 = *(const ulonglong2*)&g_conf[2 * BHW + p0];
        uint64_t m0 = 0, m1 = 0;
        FMA2(m0, c3.x, a3p0, m0); FMA2(m0, c5.x, a5p0, m0); FMA2(m0, c7.x, a7p0, m0);
        FMA2(m1, c3.y, a3p1, m1); FMA2(m1, c5.y, a5p1, m1); FMA2(m1, c7.y, a7p1, m1);
        *(uint64_t*)&g_hns[(size_t)mixidx * BHW + p0]     = m0;
        *(uint64_t*)&g_hns[(size_t)mixidx * BHW + p0 + 2] = m1;
    }
}

// ---------------- K5: final conv(67ch,3x3) -> softmax -> blend ------------------
#define FTX 16
#define FTY 8
__global__ __launch_bounds__(128) void final_kernel(const float* __restrict__ fout,
                                                    const float* __restrict__ ctw,
                                                    const float* __restrict__ ctb,
                                                    float* __restrict__ out) {
    __shared__ float wct[3 * 67 * 9];
    __shared__ float tile[(FTY+2)*(FTX+2)];
    int tid = threadIdx.x;
    int tx = tid & (FTX-1);
    int ty = tid >> 4;
    int bidx = blockIdx.x;
    const int bw = Ww / FTX;
    const int bh = Hh / FTY;
    int bx = bidx % bw;
    int t2 = bidx / bw;
    int by = t2 % bh;
    int b  = t2 / bh;
    int x0 = bx * FTX, y0 = by * FTY;

    for (int i = tid; i < 3 * 67 * 9; i += 128) wct[i] = ctw[i];

    float acc0 = 0.f, acc1 = 0.f, acc2 = 0.f;
    for (int ic = 0; ic < 67; ic++) {
        const float* src = (ic < 64)
            ? fout + ((size_t)(b * Cc + ic)) * HW
            : g_hns + (size_t)(ic - 64) * BHW + (size_t)b * HW;
        __syncthreads();
        for (int i = tid; i < (FTY+2)*(FTX+2); i += 128) {
            int yy = i / (FTX+2), xx = i % (FTX+2);
            int gy = y0 + yy - 1, gx = x0 + xx - 1;
            float v = 0.f;
            if (gy >= 0 && gy < Hh && gx >= 0 && gx < Ww) v = src[gy * Ww + gx];
            tile[i] = v;
        }
        __syncthreads();
        float xv[9];
#pragma unroll
        for (int ky = 0; ky < 3; ky++)
#pragma unroll
            for (int kx = 0; kx < 3; kx++)
                xv[ky * 3 + kx] = tile[(ty + ky) * (FTX+2) + tx + kx];
#pragma unroll
        for (int k = 0; k < 9; k++) {
            acc0 = fmaf(wct[(0 * 67 + ic) * 9 + k], xv[k], acc0);
            acc1 = fmaf(wct[(1 * 67 + ic) * 9 + k], xv[k], acc1);
            acc2 = fmaf(wct[(2 * 67 + ic) * 9 + k], xv[k], acc2);
        }
    }

    int p = (b * Hh + y0 + ty) * Ww + x0 + tx;
    float l0 = acc0 + ctb[0];
    float l1 = acc1 + ctb[1];
    float l2 = acc2 + ctb[2];
    float m = fmaxf(l0, fmaxf(l1, l2));
    float e0 = __expf(l0 - m), e1 = __expf(l1 - m), e2 = __expf(l2 - m);
    float is = 1.f / (e0 + e1 + e2);
    float h0v = g_hns[p], h1v = g_hns[BHW + p], h2v = g_hns[2 * BHW + p];
    out[p] = (e0 * h0v + e1 * h1v + e2 * h2v) * is;
}

// ---------------- launch --------------------------------------------------------
extern "C" void kernel_launch(void* const* d_in, const int* in_sizes, int n_in,
                              void* d_out, int out_size) {
    const float* fout = (const float*)d_in[0];
    const float* hn   = (const float*)d_in[1];
    const float* w3c  = (const float*)d_in[3];
    const float* w3g  = (const float*)d_in[4];
    const float* w3b  = (const float*)d_in[5];
    const float* w5c  = (const float*)d_in[6];
    const float* w5g  = (const float*)d_in[7];
    const float* w5b  = (const float*)d_in[8];
    const float* w7c  = (const float*)d_in[9];
    const float* w7g  = (const float*)d_in[10];
    const float* w7b  = (const float*)d_in[11];
    const float* ckw  = (const float*)d_in[12];
    const float* ckb  = (const float*)d_in[13];
    const float* ctw  = (const float*)d_in[14];
    const float* ctb  = (const float*)d_in[15];
    const float* s3   = (const float*)d_in[16];
    const float* s5   = (const float*)d_in[17];
    const float* s7   = (const float*)d_in[18];
    float* out = (float*)d_out;

    {
        int n = 64 * NOCP * 9;
        reorg_kernel<<<(n + 255) / 256, 256>>>(w3c, w5c, w7c, ckw);
    }
    // keep profiled slot (4th launch) on conv83
    noop_kernel<<<1, 32>>>();
    noop_kernel<<<1, 32>>>();
    {
        dim3 g((Ww / CTILEW) * 6, Hh / CTY, Bb);   // 30 x 32 x 4
        conv83_kernel<<<g, 128>>>(fout);
    }
    {
        dim3 g(80, 64);
        stats_kernel<<<g, 256>>>();
    }
    finalize_kernel<<<1, 96>>>(w3g, w3b, w5g, w5b, w7g, w7b, ckb, s3, s5, s7);
    gen_weights_kernel<<<BHW / 512, 256>>>(hn);
    {
        dim3 g(Ww / PTW, Hh / PTH, Bb);
        prop_kernel<<<g, 256>>>(1, -1);
        prop_kernel<<<g, 256>>>(0, -1);
        prop_kernel<<<g, 256>>>(1,  1);
        prop_kernel<<<g, 256>>>(0, -1);
        prop_kernel<<<g, 256>>>(1, -1);
        prop_kernel<<<g, 256>>>(0,  2);
    }
    final_kernel<<<(Ww/FTX) * (Hh/FTY) * Bb, 128>>>(fout, ctw, ctb, out);
}

// round 8
// speedup vs baseline: 1.4305x; 1.0035x over previous
#include <cuda_runtime.h>
#include <cstdint>

#define Bb 4
#define Cc 64
#define Hh 256
#define Ww 320
#define HW (Hh*Ww)
#define BHW (Bb*HW)
#define NOC 83          // 8 (w3) + 24 (w5) + 48 (w7) + 3 (ck)
#define NOCP 84         // padded to 6 groups of 14
#define NWK 83
#define EPSW 1e-6f
#define BN_EPS 1e-5f

// ---------------- device scratch ------------------------------------------------
__device__ float g_wflat[64 * (NOCP*9)];
__device__ float g_convout[(size_t)NOCP * BHW];
__device__ float g_stats[2 * NOC];
__device__ float g_scale[NOC];
__device__ float g_shift[NOC];
__device__ float g_spatial[NWK];
__device__ float g_weights[(size_t)NWK * BHW];
__device__ float g_conf[3 * BHW];
__device__ float g_hnA[3 * BHW];
__device__ float g_hnB[3 * BHW];
__device__ float g_hns[3 * BHW];

// packed dual-fp32 FMA (sm_100+)
#define FMA2(d, a, b, c) \
    asm("fma.rn.f32x2 %0, %1, %2, %3;" : "=l"(d) : "l"(a), "l"(b), "l"(c))

__device__ __forceinline__ uint64_t pk2(float lo, float hi) {
    uint64_t r; asm("mov.b64 %0,{%1,%2};" : "=l"(r) : "f"(lo), "f"(hi)); return r;
}

__global__ void noop_kernel() {}

// ---------------- K0: reorder conv weights (pad oc 83 with zeros) --------------
__global__ void reorg_kernel(const float* __restrict__ w3, const float* __restrict__ w5,
                             const float* __restrict__ w7, const float* __restrict__ ck) {
    int i = blockIdx.x * blockDim.x + threadIdx.x;
    if (i < 2 * NOC) g_stats[i] = 0.f;
    if (i >= 64 * NOCP * 9) return;
    int k  = i % 9;
    int t  = i / 9;
    int oc = t % NOCP;
    int c  = t / NOCP;
    float v;
    if (oc < 8)        v = w3[(oc      * 64 + c) * 9 + k];
    else if (oc < 32)  v = w5[((oc-8)  * 64 + c) * 9 + k];
    else if (oc < 80)  v = w7[((oc-32) * 64 + c) * 9 + k];
    else if (oc < 83)  v = ck[((oc-80) * 64 + c) * 9 + k];
    else               v = 0.f;
    g_wflat[c * (NOCP*9) + oc * 9 + k] = v;
}

// ---------------- K1: 3x3 conv, FFMA2, 14 oc/block, 4 px/thread, 2ch/phase -----
#define CTY 8
#define CTILEW 64
#define CSTR 68          // smem row stride floats (66 used)
__global__ __launch_bounds__(128, 3) void conv83_kernel(const float* __restrict__ fout) {
    __shared__ __align__(16) float tile[2][10 * CSTR];
    __shared__ __align__(16) float wsm[2][14 * 20];   // weights splatted to pairs

    int tid = threadIdx.x;
    int tx = tid & 15;           // 0..15, 4 px each
    int ty = tid >> 4;           // 0..7
    int gb = blockIdx.x;
    int grp = gb % 6;            // group fastest -> shared tile in L2
    int bx  = gb / 6;            // 0..4
    int by  = blockIdx.y;        // 0..31
    int b   = blockIdx.z;
    int x0 = bx * CTILEW, y0 = by * CTY;
    int ocbase = grp * 14;

    uint64_t acc[28];            // 14 oc x 2 pixel-pairs
#pragma unroll
    for (int i = 0; i < 28; i++) acc[i] = 0ull;

    for (int c0 = 0; c0 < Cc; c0 += 2) {
        // load 2 channel tiles (10 x 66, halo 1, zero-padded)
#pragma unroll
        for (int cc = 0; cc < 2; cc++) {
            const float* src = fout + ((size_t)(b * Cc + c0 + cc)) * HW;
            for (int i = tid; i < 10 * 66; i += 128) {
                int r = i / 66, col = i - r * 66;
                int gy = y0 + r - 1, gx = x0 + col - 1;
                float v = 0.f;
                if (gy >= 0 && gy < Hh && gx >= 0 && gx < Ww) v = src[gy * Ww + gx];
                tile[cc][r * CSTR + col] = v;
            }
        }
        // load + splat weights for both channels
        for (int i = tid; i < 2 * 14 * 9; i += 128) {
            int cc = i / 126;
            int r  = i - cc * 126;
            int oc = r / 9, k = r - oc * 9;
            float w = g_wflat[(size_t)(c0 + cc) * (NOCP*9) + (ocbase + oc) * 9 + k];
            wsm[cc][oc * 20 + 2*k]     = w;
            wsm[cc][oc * 20 + 2*k + 1] = w;
        }
        __syncthreads();

#pragma unroll
        for (int cc = 0; cc < 2; cc++) {
            // per row: 6 values v[0..5] -> 5 packed pairs pr[j]=(v[j],v[j+1])
            uint64_t pr[3][5];
#pragma unroll
            for (int r = 0; r < 3; r++) {
                const float* row = &tile[cc][(ty + r) * CSTR + tx * 4];
                float4 q = *(const float4*)row;
                float2 d = *(const float2*)(row + 4);
                pr[r][0] = pk2(q.x, q.y);
                pr[r][1] = pk2(q.y, q.z);
                pr[r][2] = pk2(q.z, q.w);
                pr[r][3] = pk2(q.w, d.x);
                pr[r][4] = pk2(d.x, d.y);
            }
            const ulonglong2* wq = (const ulonglong2*)wsm[cc];
#pragma unroll
            for (int oc = 0; oc < 14; oc++) {
                ulonglong2 w01 = wq[oc * 5 + 0];
                ulonglong2 w23 = wq[oc * 5 + 1];
                ulonglong2 w45 = wq[oc * 5 + 2];
                ulonglong2 w67 = wq[oc * 5 + 3];
                uint64_t   w8  = ((const uint64_t*)wsm[cc])[oc * 10 + 8];
                uint64_t w[9] = {w01.x, w01.y, w23.x, w23.y, w45.x, w45.y, w67.x, w67.y, w8};
                uint64_t a0 = acc[oc * 2], a1 = acc[oc * 2 + 1];
#pragma unroll
                for (int ky = 0; ky < 3; ky++) {
#pragma unroll
                    for (int kx = 0; kx < 3; kx++) {
                        uint64_t wk = w[ky * 3 + kx];
                        FMA2(a0, wk, pr[ky][kx],     a0);
                        FMA2(a1, wk, pr[ky][kx + 2], a1);
                    }
                }
                acc[oc * 2] = a0; acc[oc * 2 + 1] = a1;
            }
        }
        __syncthreads();
    }

    int p = (b * Hh + y0 + ty) * Ww + x0 + tx * 4;
#pragma unroll
    for (int oc = 0; oc < 14; oc++) {
        ulonglong2 st; st.x = acc[oc * 2]; st.y = acc[oc * 2 + 1];
        *(ulonglong2*)&g_convout[(size_t)(ocbase + oc) * BHW + p] = st;
    }
}

// ---------------- K2a: per-channel sum / sumsq ----------------------------------
__global__ void stats_kernel() {
    int oc = blockIdx.x;
    const int CHUNK = BHW / 64;
    const float* src = g_convout + (size_t)oc * BHW + blockIdx.y * CHUNK;
    float s = 0.f, s2 = 0.f;
    for (int i = threadIdx.x; i < CHUNK; i += 256) {
        float v = src[i];
        s += v;
        s2 = fmaf(v, v, s2);
    }
#pragma unroll
    for (int o = 16; o; o >>= 1) {
        s  += __shfl_down_sync(0xffffffffu, s,  o);
        s2 += __shfl_down_sync(0xffffffffu, s2, o);
    }
    __shared__ float sh[16];
    int w = threadIdx.x >> 5, l = threadIdx.x & 31;
    if (l == 0) { sh[w] = s; sh[8 + w] = s2; }
    __syncthreads();
    if (threadIdx.x == 0) {
        float a = 0.f, b2 = 0.f;
        for (int i = 0; i < 8; i++) { a += sh[i]; b2 += sh[8 + i]; }
        atomicAdd(&g_stats[oc], a);
        atomicAdd(&g_stats[NOC + oc], b2);
    }
}

// ---------------- K2b: finalize BN affine + spatial table -----------------------
__global__ void finalize_kernel(const float* __restrict__ w3g, const float* __restrict__ w3b,
                                const float* __restrict__ w5g, const float* __restrict__ w5b,
                                const float* __restrict__ w7g, const float* __restrict__ w7b,
                                const float* __restrict__ ckb,
                                const float* __restrict__ ps3,
                                const float* __restrict__ ps5,
                                const float* __restrict__ ps7) {
    int oc = threadIdx.x;
    if (oc < NWK) {
        int pk, kk, kb;
        float sig;
        if (oc < 9)       { pk = 3; kb = 0;  sig = *ps3; }
        else if (oc < 34) { pk = 5; kb = 9;  sig = *ps5; }
        else              { pk = 7; kb = 34; sig = *ps7; }
        kk = oc - kb;
        int ki = kk / pk, kj = kk % pk;
        float ri = -1.f + 2.f * (float)ki / (float)(pk - 1);
        float rj = -1.f + 2.f * (float)kj / (float)(pk - 1);
        g_spatial[oc] = __expf(-(ri * ri + rj * rj) / (2.f * sig * sig));
    }
    if (oc >= NOC) return;
    if (oc < 80) {
        float N = (float)BHW;
        float mean = g_stats[oc] / N;
        float var  = g_stats[NOC + oc] / N - mean * mean;
        float inv  = rsqrtf(var + BN_EPS);
        float g, bb;
        if (oc < 8)       { g = w3g[oc];      bb = w3b[oc]; }
        else if (oc < 32) { g = w5g[oc - 8];  bb = w5b[oc - 8]; }
        else              { g = w7g[oc - 32]; bb = w7b[oc - 32]; }
        g_scale[oc] = g * inv;
        g_shift[oc] = bb - mean * g * inv;
    } else {
        g_scale[oc] = 1.f;
        g_shift[oc] = ckb[oc - 80];
    }
}

// ---------------- K3: per-pixel kernel generation (2 px/thread) -----------------
template <int NC, int PK>
__device__ __forceinline__ void gen_group2(int p, int ocbase, int kbase, const float* __restrict__ sp) {
    const int KK = PK * PK;
    float w0[NC], w1[NC];
    float s0 = 0.f, s1 = 0.f;
#pragma unroll
    for (int j = 0; j < NC; j++) {
        float2 x = *(const float2*)&g_convout[(size_t)(ocbase + j) * BHW + p];
        float sc = g_scale[ocbase + j], sh = g_shift[ocbase + j];
        float a = fmaxf(fmaf(sc, x.x, sh), 0.f);
        float b = fmaxf(fmaf(sc, x.y, sh), 0.f);
        w0[j] = a; w1[j] = b;
        s0 += a;  s1 += b;
    }
    float i0 = 1.f / (s0 + EPSW), i1 = 1.f / (s1 + EPSW);
    float mid0 = 1.f - s0 * i0,   mid1 = 1.f - s1 * i1;
    const int h = (KK - 1) / 2;
    float f0[KK], f1[KK];
#pragma unroll
    for (int j = 0; j < h; j++) { f0[j] = w0[j] * i0; f1[j] = w1[j] * i1; }
    f0[h] = mid0; f1[h] = mid1;
#pragma unroll
    for (int j = 0; j < NC - h; j++) { f0[h+1+j] = w0[h+j] * i0; f1[h+1+j] = w1[h+j] * i1; }

    float t0 = 0.f, t1 = 0.f;
#pragma unroll
    for (int k = 0; k < KK; k++) {
        float sk = sp[kbase + k];
        f0[k] *= sk; f1[k] *= sk;
        t0 += f0[k]; t1 += f1[k];
    }
    float it0 = 1.f / fmaxf(t0, 1e-7f);
    float it1 = 1.f / fmaxf(t1, 1e-7f);
#pragma unroll
    for (int k = 0; k < KK; k++) {
        float2 o; o.x = f0[k] * it0; o.y = f1[k] * it1;
        *(float2*)&g_weights[(size_t)(kbase + k) * BHW + p] = o;
    }
}

__global__ __launch_bounds__(256) void gen_weights_kernel(const float* __restrict__ hn) {
    __shared__ float ssp[NWK];
    int tid = threadIdx.x;
    if (tid < NWK) ssp[tid] = g_spatial[tid];
    __syncthreads();
    int p = 2 * (blockIdx.x * 256 + tid);
    if (p >= BHW) return;
    gen_group2<8, 3>(p, 0, 0, ssp);
    gen_group2<24, 5>(p, 8, 9, ssp);
    gen_group2<48, 7>(p, 32, 34, ssp);

    float2 l0 = *(const float2*)&g_convout[(size_t)80 * BHW + p];
    float2 l1 = *(const float2*)&g_convout[(size_t)81 * BHW + p];
    float2 l2 = *(const float2*)&g_convout[(size_t)82 * BHW + p];
    float s80 = g_shift[80], s81 = g_shift[81], s82 = g_shift[82];
#pragma unroll
    for (int hfi = 0; hfi < 2; hfi++) {
        float a = (hfi ? l0.y : l0.x) + s80;
        float b = (hfi ? l1.y : l1.x) + s81;
        float c = (hfi ? l2.y : l2.x) + s82;
        float m = fmaxf(a, fmaxf(b, c));
        float e0 = __expf(a - m), e1 = __expf(b - m), e2 = __expf(c - m);
        float is = 1.f / (e0 + e1 + e2);
        g_conf[p + hfi] = e0 * is;
        g_conf[BHW + p + hfi] = e1 * is;
        g_conf[2 * BHW + p + hfi] = e2 * is;
    }
    float2 hv = *(const float2*)&hn[p];
    *(float2*)&g_hnA[p] = hv;
    *(float2*)&g_hnA[BHW + p] = hv;
    *(float2*)&g_hnA[2 * BHW + p] = hv;
    *(float2*)&g_hns[p] = hv;
}

// ---------------- K4: propagation, smem-tiled, 4 px/thread, FFMA2 ---------------
#define PTW 64
#define PTH 16
#define PSW 72
__device__ __forceinline__ void build_pr(const float* __restrict__ rowp, uint64_t pr[9]) {
    float2 f0 = *(const float2*)(rowp);
    float2 f1 = *(const float2*)(rowp + 2);
    float2 f2 = *(const float2*)(rowp + 4);
    float2 f3 = *(const float2*)(rowp + 6);
    float2 f4 = *(const float2*)(rowp + 8);
    pr[0] = pk2(f0.x, f0.y);
    pr[1] = pk2(f0.y, f1.x);
    pr[2] = pk2(f1.x, f1.y);
    pr[3] = pk2(f1.y, f2.x);
    pr[4] = pk2(f2.x, f2.y);
    pr[5] = pk2(f2.y, f3.x);
    pr[6] = pk2(f3.x, f3.y);
    pr[7] = pk2(f3.y, f4.x);
    pr[8] = pk2(f4.x, f4.y);
}

__global__ __launch_bounds__(256) void prop_kernel(int srcA, int mixidx) {
    __shared__ __align__(16) float sh[3][PTH + 6][PSW];
    const float* cur = srcA ? g_hnA : g_hnB;
    float* nxt = srcA ? g_hnB : g_hnA;

    int tid = threadIdx.x;
    int tx = tid & 15;
    int ty = tid >> 4;
    int bx = blockIdx.x;
    int by = blockIdx.y;
    int b  = blockIdx.z;
    int x0 = bx * PTW, y0 = by * PTH;

#pragma unroll
    for (int c = 0; c < 3; c++) {
        const float* plane = cur + (size_t)c * BHW + (size_t)b * HW;
        for (int i = tid; i < (PTH + 6) * 70; i += 256) {
            int r = i / 70, col = i - r * 70;
            int gy = y0 + r - 3, gx = x0 + col - 3;
            float v = 0.f;
            if (gy >= 0 && gy < Hh && gx >= 0 && gx < Ww) v = plane[gy * Ww + gx];
            sh[c][r][col] = v;
        }
    }
    __syncthreads();

    int xl = tx * 4;
    int p0 = (b * Hh + y0 + ty) * Ww + x0 + xl;

    uint64_t a3p0 = 0, a3p1 = 0, a5p0 = 0, a5p1 = 0, a7p0 = 0, a7p1 = 0;
    uint64_t pr[9];

#pragma unroll
    for (int ky = 0; ky < 3; ky++) {
        build_pr(&sh[0][ty + 2 + ky][xl], pr);
#pragma unroll
        for (int kx = 0; kx < 3; kx++) {
            const ulonglong2 wq = *(const ulonglong2*)&g_weights[(size_t)(0 + ky * 3 + kx) * BHW + p0];
            FMA2(a3p0, wq.x, pr[kx + 2], a3p0);
            FMA2(a3p1, wq.y, pr[kx + 4], a3p1);
        }
    }
#pragma unroll
    for (int ky = 0; ky < 5; ky++) {
        build_pr(&sh[1][ty + 1 + ky][xl], pr);
#pragma unroll
        for (int kx = 0; kx < 5; kx++) {
            const ulonglong2 wq = *(const ulonglong2*)&g_weights[(size_t)(9 + ky * 5 + kx) * BHW + p0];
            FMA2(a5p0, wq.x, pr[kx + 1], a5p0);
            FMA2(a5p1, wq.y, pr[kx + 3], a5p1);
        }
    }
#pragma unroll
    for (int ky = 0; ky < 7; ky++) {
        build_pr(&sh[2][ty + ky][xl], pr);
#pragma unroll
        for (int kx = 0; kx < 7; kx++) {
            const ulonglong2 wq = *(const ulonglong2*)&g_weights[(size_t)(34 + ky * 7 + kx) * BHW + p0];
            FMA2(a7p0, wq.x, pr[kx], a7p0);
            FMA2(a7p1, wq.y, pr[kx + 2], a7p1);
        }
    }

    *(uint64_t*)&nxt[p0]               = a3p0;
    *(uint64_t*)&nxt[p0 + 2]           = a3p1;
    *(uint64_t*)&nxt[BHW + p0]         = a5p0;
    *(uint64_t*)&nxt[BHW + p0 + 2]     = a5p1;
    *(uint64_t*)&nxt[2 * BHW + p0]     = a7p0;
    *(uint64_t*)&nxt[2 * BHW + p0 + 2] = a7p1;

    if (mixidx >= 0) {
        const ulonglong2 c3 = *(const ulonglong2*)&g_conf[p0];
        const ulonglong2 c5 = *(const ulonglong2*)&g_conf[BHW + p0];
        const ulonglong2 c7 = *(const ulonglong2*)&g_conf[2 * BHW + p0];
        uint64_t m0 = 0, m1 = 0;
        FMA2(m0, c3.x, a3p0, m0); FMA2(m0, c5.x, a5p0, m0); FMA2(m0, c7.x, a7p0, m0);
        FMA2(m1, c3.y, a3p1, m1); FMA2(m1, c5.y, a5p1, m1); FMA2(m1, c7.y, a7p1, m1);
        *(uint64_t*)&g_hns[(size_t)mixidx * BHW + p0]     = m0;
        *(uint64_t*)&g_hns[(size_t)mixidx * BHW + p0 + 2] = m1;
    }
}

// ---------------- K5: final conv(67ch,3x3) -> softmax -> blend ------------------
#define FTX 16
#define FTY 8
__global__ __launch_bounds__(128) void final_kernel(const float* __restrict__ fout,
                                                    const float* __restrict__ ctw,
                                                    const float* __restrict__ ctb,
                                                    float* __restrict__ out) {
    __shared__ float wct[3 * 67 * 9];
    __shared__ float tile[(FTY+2)*(FTX+2)];
    int tid = threadIdx.x;
    int tx = tid & (FTX-1);
    int ty = tid >> 4;
    int bidx = blockIdx.x;
    const int bw = Ww / FTX;
    const int bh = Hh / FTY;
    int bx = bidx % bw;
    int t2 = bidx / bw;
    int by = t2 % bh;
    int b  = t2 / bh;
    int x0 = bx * FTX, y0 = by * FTY;

    for (int i = tid; i < 3 * 67 * 9; i += 128) wct[i] = ctw[i];

    float acc0 = 0.f, acc1 = 0.f, acc2 = 0.f;
    for (int ic = 0; ic < 67; ic++) {
        const float* src = (ic < 64)
            ? fout + ((size_t)(b * Cc + ic)) * HW
            : g_hns + (size_t)(ic - 64) * BHW + (size_t)b * HW;
        __syncthreads();
        for (int i = tid; i < (FTY+2)*(FTX+2); i += 128) {
            int yy = i / (FTX+2), xx = i % (FTX+2);
            int gy = y0 + yy - 1, gx = x0 + xx - 1;
            float v = 0.f;
            if (gy >= 0 && gy < Hh && gx >= 0 && gx < Ww) v = src[gy * Ww + gx];
            tile[i] = v;
        }
        __syncthreads();
        float xv[9];
#pragma unroll
        for (int ky = 0; ky < 3; ky++)
#pragma unroll
            for (int kx = 0; kx < 3; kx++)
                xv[ky * 3 + kx] = tile[(ty + ky) * (FTX+2) + tx + kx];
#pragma unroll
        for (int k = 0; k < 9; k++) {
            acc0 = fmaf(wct[(0 * 67 + ic) * 9 + k], xv[k], acc0);
            acc1 = fmaf(wct[(1 * 67 + ic) * 9 + k], xv[k], acc1);
            acc2 = fmaf(wct[(2 * 67 + ic) * 9 + k], xv[k], acc2);
        }
    }

    int p = (b * Hh + y0 + ty) * Ww + x0 + tx;
    float l0 = acc0 + ctb[0];
    float l1 = acc1 + ctb[1];
    float l2 = acc2 + ctb[2];
    float m = fmaxf(l0, fmaxf(l1, l2));
    float e0 = __expf(l0 - m), e1 = __expf(l1 - m), e2 = __expf(l2 - m);
    float is = 1.f / (e0 + e1 + e2);
    float h0v = g_hns[p], h1v = g_hns[BHW + p], h2v = g_hns[2 * BHW + p];
    out[p] = (e0 * h0v + e1 * h1v + e2 * h2v) * is;
}

// ---------------- launch --------------------------------------------------------
extern "C" void kernel_launch(void* const* d_in, const int* in_sizes, int n_in,
                              void* d_out, int out_size) {
    const float* fout = (const float*)d_in[0];
    const float* hn   = (const float*)d_in[1];
    const float* w3c  = (const float*)d_in[3];
    const float* w3g  = (const float*)d_in[4];
    const float* w3b  = (const float*)d_in[5];
    const float* w5c  = (const float*)d_in[6];
    const float* w5g  = (const float*)d_in[7];
    const float* w5b  = (const float*)d_in[8];
    const float* w7c  = (const float*)d_in[9];
    const float* w7g  = (const float*)d_in[10];
    const float* w7b  = (const float*)d_in[11];
    const float* ckw  = (const float*)d_in[12];
    const float* ckb  = (const float*)d_in[13];
    const float* ctw  = (const float*)d_in[14];
    const float* ctb  = (const float*)d_in[15];
    const float* s3   = (const float*)d_in[16];
    const float* s5   = (const float*)d_in[17];
    const float* s7   = (const float*)d_in[18];
    float* out = (float*)d_out;

    {
        int n = 64 * NOCP * 9;
        reorg_kernel<<<(n + 255) / 256, 256>>>(w3c, w5c, w7c, ckw);
    }
    // keep profiled slot (4th launch) on conv83
    noop_kernel<<<1, 32>>>();
    noop_kernel<<<1, 32>>>();
    {
        dim3 g((Ww / CTILEW) * 6, Hh / CTY, Bb);   // 30 x 32 x 4
        conv83_kernel<<<g, 128>>>(fout);
    }
    {
        dim3 g(80, 64);
        stats_kernel<<<g, 256>>>();
    }
    finalize_kernel<<<1, 96>>>(w3g, w3b, w5g, w5b, w7g, w7b, ckb, s3, s5, s7);
    gen_weights_kernel<<<BHW / 512, 256>>>(hn);
    {
        dim3 g(Ww / PTW, Hh / PTH, Bb);
        prop_kernel<<<g, 256>>>(1, -1);
        prop_kernel<<<g, 256>>>(0, -1);
        prop_kernel<<<g, 256>>>(1,  1);
        prop_kernel<<<g, 256>>>(0, -1);
        prop_kernel<<<g, 256>>>(1, -1);
        prop_kernel<<<g, 256>>>(0,  2);
    }
    final_kernel<<<(Ww/FTX) * (Hh/FTY) * Bb, 128>>>(fout, ctw, ctb, out);
}